// round 11
// baseline (speedup 1.0000x reference)
#include <cuda_runtime.h>
#include <cuda_bf16.h>
#include <float.h>

// Problem constants
#define Bv 4
#define Lv 2048
#define Hv 8
#define Dv 64
#define SKv 40      // sample_k
#define Uv 40       // top-u
#define NCAND 64
#define BHv 32
#define NCH 32      // cumsum chunks (64 rows each)
#define CROWS 64
#define CK 128      // attention key-chunk size
#define NC 16       // Lv / CK
#define SCALEF 0.125f
#define KELEMS (Bv * Lv * Hv * Dv)

#define MB_BLOCKS 8192
#define SUM_BLOCKS 256
#define ATTN_BLOCKS (BHv * NC)   // 512
#define CUM_BLOCKS 256

// -------- scratch --------
__device__ float        g_M[BHv * Lv];
__device__ int          g_Mtop[BHv * Uv];      // sorted by qi DESCENDING
__device__ float        g_part[BHv * NCH * Dv];
__device__ float        g_accP[BHv * NC * Uv * 66];
__device__ __nv_bfloat16 g_Kbf[KELEMS];
__device__ int          g_is64;

// ============ K-A: bf16 K shadow + index dtype detect ============
__global__ void k_conv(const float* __restrict__ Kt, const int* __restrict__ idx32) {
    if (blockIdx.x == 0 && threadIdx.x < 32) {
        int lane = threadIdx.x;
        int bad = 0;
        for (int j = lane; j < 64; j += 32)
            bad |= (idx32[2 * j + 1] != 0);
        unsigned any = __ballot_sync(0xffffffffu, bad);
        if (lane == 0) g_is64 = (any == 0) ? 1 : 0;
    }
    int idx = (blockIdx.x * 256 + threadIdx.x) * 8;
    float4 a = *(const float4*)(Kt + idx);
    float4 b = *(const float4*)(Kt + idx + 4);
    union { __nv_bfloat162 h[4]; uint4 u; } pk;
    pk.h[0] = __float22bfloat162_rn(make_float2(a.x, a.y));
    pk.h[1] = __float22bfloat162_rn(make_float2(a.z, a.w));
    pk.h[2] = __float22bfloat162_rn(make_float2(b.x, b.y));
    pk.h[3] = __float22bfloat162_rn(make_float2(b.z, b.w));
    *(uint4*)(g_Kbf + idx) = pk.u;
}

// ============ K-B: approx M (bf16 gather) ++ V chunk sums ============
__global__ void k_MbSum(const float* __restrict__ Q, const void* __restrict__ idxraw,
                        const float* __restrict__ V) {
    if (blockIdx.x < MB_BLOCKS) {
        int warp = (blockIdx.x * 256 + threadIdx.x) >> 5;
        int i  = warp & (Lv - 1);
        int bh = warp >> 11;
        int b = bh >> 3, h = bh & 7;
        int lane = threadIdx.x & 31;
        int grp = lane >> 3;
        int j   = lane & 7;

        const int is64 = g_is64;
        const long long* i64 = (const long long*)idxraw;
        const int*       i32 = (const int*)idxraw;

        int rows[10];
#pragma unroll
        for (int p = 0; p < 10; ++p) {
            int s = p * 4 + grp;
            rows[p] = is64 ? (int)i64[i * SKv + s] : i32[i * SKv + s];
        }
        uint4 u[10];
#pragma unroll
        for (int p = 0; p < 10; ++p)
            u[p] = *(const uint4*)(g_Kbf + ((((b << 11) + rows[p]) * Hv + h) << 6) + j * 8);

        const float* qr = Q + ((((b << 11) + i) * Hv + h) << 6);
        float4 qa = *(const float4*)(qr + j * 8);
        float4 qb = *(const float4*)(qr + j * 8 + 4);

        float lmax = -FLT_MAX, lsum = 0.f;
#pragma unroll
        for (int p = 0; p < 10; ++p) {
            const __nv_bfloat162* hp = (const __nv_bfloat162*)&u[p];
            float2 k0 = __bfloat1622float2(hp[0]);
            float2 k1 = __bfloat1622float2(hp[1]);
            float2 k2 = __bfloat1622float2(hp[2]);
            float2 k3 = __bfloat1622float2(hp[3]);
            float d = qa.x * k0.x + qa.y * k0.y + qa.z * k1.x + qa.w * k1.y
                    + qb.x * k2.x + qb.y * k2.y + qb.z * k3.x + qb.w * k3.y;
            d += __shfl_xor_sync(0xffffffffu, d, 1);
            d += __shfl_xor_sync(0xffffffffu, d, 2);
            d += __shfl_xor_sync(0xffffffffu, d, 4);
            lmax = fmaxf(lmax, d);
            lsum += d;
        }
        lmax = fmaxf(lmax, __shfl_xor_sync(0xffffffffu, lmax, 8));
        lmax = fmaxf(lmax, __shfl_xor_sync(0xffffffffu, lmax, 16));
        lsum += __shfl_xor_sync(0xffffffffu, lsum, 8);
        lsum += __shfl_xor_sync(0xffffffffu, lsum, 16);
        if (lane == 0)
            g_M[bh * Lv + i] = lmax - lsum * (1.0f / (float)Lv);
    } else {
        int bid = blockIdx.x - MB_BLOCKS;
        int bh = bid >> 3, cg = bid & 7;
        int b = bh >> 3, h = bh & 7;
        int sub = threadIdx.x >> 6, d = threadIdx.x & 63;
        int chunk = cg * 4 + sub;
        int base = (((b * Lv + chunk * CROWS) * Hv + h) << 6) + d;
        const int stride = Hv * Dv;
        float run = 0.f;
        for (int r0 = 0; r0 < CROWS; r0 += 8) {
            float v[8];
#pragma unroll
            for (int q = 0; q < 8; ++q) v[q] = V[base + (r0 + q) * stride];
#pragma unroll
            for (int q = 0; q < 8; ++q) run += v[q];
        }
        g_part[(bh * NCH + chunk) * Dv + d] = run;
    }
}

// ============ K-C: sel64 -> rescore -> top40 (sorted by qi desc) ++ chunk scan ============
__device__ __forceinline__ unsigned f2u_mono(float f) {
    unsigned u = __float_as_uint(f);
    return (u & 0x80000000u) ? ~u : (u | 0x80000000u);
}

__global__ void k_selScan(const float* __restrict__ Q, const float* __restrict__ Kt,
                          const void* __restrict__ idxraw) {
    __shared__ unsigned keys[Lv];
    __shared__ int hist[256];
    __shared__ int cand_sm[NCAND];
    __shared__ float mex_sm[NCAND];
    __shared__ int selqi[NCAND];
    __shared__ int s_pref, s_rem, s_remN, s_cnt, s_eq;

    if (blockIdx.x >= 32) {
        // ---- scanB: exclusive scan of 32 chunk partials, full-MLP ----
        int bh = blockIdx.x - 32;
        int d = threadIdx.x;
        if (d < 64) {
            float v[NCH];
#pragma unroll
            for (int c = 0; c < NCH; ++c) v[c] = g_part[(bh * NCH + c) * Dv + d];
            float ex = 0.f;
#pragma unroll
            for (int c = 0; c < NCH; ++c) { float tv = v[c]; v[c] = ex; ex += tv; }
#pragma unroll
            for (int c = 0; c < NCH; ++c) g_part[(bh * NCH + c) * Dv + d] = v[c];
        }
        return;
    }

    int bh = blockIdx.x, t = threadIdx.x;
    int b = bh >> 3, h = bh & 7;

    for (int e = t; e < Lv; e += 256)
        keys[e] = f2u_mono(g_M[bh * Lv + e]);
    if (t == 0) { s_pref = 0; s_rem = NCAND; s_cnt = 0; s_eq = 0; }
    __syncthreads();

    unsigned pmask = 0;
#pragma unroll
    for (int pass = 0; pass < 4; ++pass) {
        int shift = 24 - pass * 8;
        hist[t] = 0;
        __syncthreads();
        unsigned pref = (unsigned)s_pref;
        for (int e = t; e < Lv; e += 256) {
            unsigned k = keys[e];
            if ((k & pmask) == pref)
                atomicAdd(&hist[(k >> shift) & 255], 1);
        }
        __syncthreads();
        if (t < 32) {
            int lane = t;
            int h8[8]; int sl = 0;
#pragma unroll
            for (int bb = 0; bb < 8; ++bb) { h8[bb] = hist[lane * 8 + bb]; sl += h8[bb]; }
            int suf = sl;
#pragma unroll
            for (int o = 1; o < 32; o <<= 1) {
                int v = __shfl_down_sync(0xffffffffu, suf, o);
                if (lane + o < 32) suf += v;
            }
            int above = suf - sl;
            int rem = s_rem;
            __syncwarp();
            int run = 0;
#pragma unroll
            for (int bb = 7; bb >= 0; --bb) {
                run += h8[bb];
                int S = above + run;
                if (S >= rem && S - h8[bb] < rem) {
                    s_pref = (int)(pref | ((unsigned)(lane * 8 + bb) << shift));
                    s_remN = rem - (S - h8[bb]);
                }
            }
        }
        __syncthreads();
        if (t == 0) s_rem = s_remN;
        pmask |= (255u << shift);
        __syncthreads();
    }
    unsigned T = (unsigned)s_pref;
    int ceq = s_rem;
    for (int e = t; e < Lv; e += 256) {
        unsigned k = keys[e];
        if (k > T) {
            int pos = atomicAdd(&s_cnt, 1);
            cand_sm[pos] = e;
        } else if (k == T) {
            int p = atomicAdd(&s_eq, 1);
            if (p < ceq) {
                int pos = atomicAdd(&s_cnt, 1);
                cand_sm[pos] = e;
            }
        }
    }
    __syncthreads();

    // ---- exact fp32 rescore: 8 warps x 8 rounds ----
    {
        int w = t >> 5, lane = t & 31;
        int grp = lane >> 3, j = lane & 7;
        const int is64 = g_is64;
        const long long* i64 = (const long long*)idxraw;
        const int*       i32 = (const int*)idxraw;
#pragma unroll 1
        for (int r = 0; r < 8; ++r) {
            int c = r * 8 + w;
            int i = cand_sm[c];
            int rows[10];
#pragma unroll
            for (int p = 0; p < 10; ++p) {
                int s = p * 4 + grp;
                rows[p] = is64 ? (int)i64[i * SKv + s] : i32[i * SKv + s];
            }
            float4 kv[10][2];
#pragma unroll
            for (int p = 0; p < 10; ++p) {
                const float* kr = Kt + ((((b << 11) + rows[p]) * Hv + h) << 6) + j * 8;
                kv[p][0] = *(const float4*)(kr);
                kv[p][1] = *(const float4*)(kr + 4);
            }
            const float* qr = Q + ((((b << 11) + i) * Hv + h) << 6);
            float4 qa = *(const float4*)(qr + j * 8);
            float4 qb = *(const float4*)(qr + j * 8 + 4);

            float lmax = -FLT_MAX, lsum = 0.f;
#pragma unroll
            for (int p = 0; p < 10; ++p) {
                float4 ka = kv[p][0], kb = kv[p][1];
                float d = qa.x * ka.x + qa.y * ka.y + qa.z * ka.z + qa.w * ka.w
                        + qb.x * kb.x + qb.y * kb.y + qb.z * kb.z + qb.w * kb.w;
                d += __shfl_xor_sync(0xffffffffu, d, 1);
                d += __shfl_xor_sync(0xffffffffu, d, 2);
                d += __shfl_xor_sync(0xffffffffu, d, 4);
                lmax = fmaxf(lmax, d);
                lsum += d;
            }
            lmax = fmaxf(lmax, __shfl_xor_sync(0xffffffffu, lmax, 8));
            lmax = fmaxf(lmax, __shfl_xor_sync(0xffffffffu, lmax, 16));
            lsum += __shfl_xor_sync(0xffffffffu, lsum, 8);
            lsum += __shfl_xor_sync(0xffffffffu, lsum, 16);
            if (lane == 0)
                mex_sm[c] = lmax - lsum * (1.0f / (float)Lv);
        }
    }
    __syncthreads();

    // ---- top-40 set by rank counting, ordered by qi DESC ----
    if (t < NCAND) {
        float mv = mex_sm[t];
        int   ci = cand_sm[t];
        int rank = 0;
#pragma unroll
        for (int jj = 0; jj < NCAND; ++jj) {
            float ov = mex_sm[jj];
            int   oi = cand_sm[jj];
            rank += (ov > mv || (ov == mv && oi < ci)) ? 1 : 0;
        }
        selqi[t] = (rank < Uv) ? ci : -1;
    }
    __syncthreads();
    if (t < NCAND && selqi[t] >= 0) {
        int ci = selqi[t];
        int pos = 0;
#pragma unroll
        for (int jj = 0; jj < NCAND; ++jj)
            pos += (selqi[jj] > ci) ? 1 : 0;    // larger qi first
        g_Mtop[bh * Uv + pos] = ci;
    }
}

// ============ K-D: [0,512): causal attention, bf16 K/V smem (63KB -> 3 blocks/SM);
//              [512,768): cumsum writer ============
// smem word layout (uint32 units): K[128][33] | V[128][33] | q f32[40][64] | p f32[40][128] | qi[40]
#define KVS 33                    // row stride in bf16x2 words (bank = (row+col)%32)
#define OFF_V  (CK * KVS)         // 4224
#define OFF_Q  (OFF_V + CK * KVS) // 8448
#define OFF_P  (OFF_Q + Uv * 64)  // 11008
#define OFF_QI (OFF_P + Uv * CK)  // 16128
#define SMEM_ATTN ((OFF_QI + Uv) * 4)   // 64672 B

__global__ void k_cumAttn(const float* __restrict__ Q, const float* __restrict__ Kt,
                          const float* __restrict__ Vt, float* __restrict__ out) {
    if (blockIdx.x >= ATTN_BLOCKS) {
        // ---- cum2: cumsum with chunk offset ----
        int bid = blockIdx.x - ATTN_BLOCKS;
        int bh = bid >> 3, cg = bid & 7;
        int b = bh >> 3, h = bh & 7;
        int sub = threadIdx.x >> 6, d = threadIdx.x & 63;
        int chunk = cg * 4 + sub;
        int base = (((b * Lv + chunk * CROWS) * Hv + h) << 6) + d;
        const int stride = Hv * Dv;
        float run = g_part[(bh * NCH + chunk) * Dv + d];
        for (int r0 = 0; r0 < CROWS; r0 += 8) {
            float v[8];
#pragma unroll
            for (int q = 0; q < 8; ++q) v[q] = Vt[base + (r0 + q) * stride];
#pragma unroll
            for (int q = 0; q < 8; ++q) { run += v[q]; out[base + (r0 + q) * stride] = run; }
        }
        return;
    }

    extern __shared__ unsigned smw[];
    unsigned* Ksm = smw;
    unsigned* Vsm = smw + OFF_V;
    float*    qsm = (float*)(smw + OFF_Q);
    float*    psm = (float*)(smw + OFF_P);
    int*      qism = (int*)(smw + OFF_QI);

    int bid = blockIdx.x;
    int bh = bid >> 4, c = bid & 15;
    int b = bh >> 3, h = bh & 7;
    int t = threadIdx.x;
    int cbase = c * CK;

    if (t < Uv) qism[t] = g_Mtop[bh * Uv + t];
    int n_act = __syncthreads_count(t < Uv && qism[t] >= cbase);
    if (n_act == 0) return;

    // stage K/V as bf16x2 rows (stride 33 words)
    const int kbase = ((b * Lv + cbase) * Hv + h) << 6;
    for (int e = t; e < CK * 16; e += 256) {
        int r = e >> 4, d4 = (e & 15) * 4;
        float4 kv = *(const float4*)(Kt + kbase + r * (Hv * Dv) + d4);
        __nv_bfloat162 ka = __float22bfloat162_rn(make_float2(kv.x, kv.y));
        __nv_bfloat162 kb = __float22bfloat162_rn(make_float2(kv.z, kv.w));
        Ksm[r * KVS + (d4 >> 1)]     = *(unsigned*)&ka;
        Ksm[r * KVS + (d4 >> 1) + 1] = *(unsigned*)&kb;
        float4 vv = *(const float4*)(Vt + kbase + r * (Hv * Dv) + d4);
        __nv_bfloat162 va = __float22bfloat162_rn(make_float2(vv.x, vv.y));
        __nv_bfloat162 vb = __float22bfloat162_rn(make_float2(vv.z, vv.w));
        Vsm[r * KVS + (d4 >> 1)]     = *(unsigned*)&va;
        Vsm[r * KVS + (d4 >> 1) + 1] = *(unsigned*)&vb;
    }
    for (int e = t; e < Uv * 16; e += 256) {
        int u = e >> 4, d4 = (e & 15) * 4;
        int qi = qism[u];
        float4 qv = *(const float4*)(Q + (((b * Lv + qi) * Hv + h) << 6) + d4);
        qv.x *= SCALEF; qv.y *= SCALEF; qv.z *= SCALEF; qv.w *= SCALEF;
        *(float4*)&qsm[u * 64 + d4] = qv;
    }
    __syncthreads();

    int w = t >> 5, kt = t & 31;

    // ---- score phase: warp w owns u = 5w+j; lanes own k = kt + 32i (4 k's) ----
    if (qism[5 * w] >= cbase) {
        float acc[5][4];
#pragma unroll
        for (int j = 0; j < 5; ++j)
#pragma unroll
            for (int i = 0; i < 4; ++i) acc[j][i] = 0.f;

#pragma unroll 4
        for (int dd2 = 0; dd2 < 32; ++dd2) {    // 2 d's per iteration
            unsigned w0 = Ksm[(kt     ) * KVS + dd2];
            unsigned w1 = Ksm[(kt + 32) * KVS + dd2];
            unsigned w2 = Ksm[(kt + 64) * KVS + dd2];
            unsigned w3 = Ksm[(kt + 96) * KVS + dd2];
            float2 k0 = __bfloat1622float2(*(__nv_bfloat162*)&w0);
            float2 k1 = __bfloat1622float2(*(__nv_bfloat162*)&w1);
            float2 k2 = __bfloat1622float2(*(__nv_bfloat162*)&w2);
            float2 k3 = __bfloat1622float2(*(__nv_bfloat162*)&w3);
#pragma unroll
            for (int j = 0; j < 5; ++j) {
                float2 qf = *(const float2*)&qsm[(5 * w + j) * 64 + dd2 * 2];
                acc[j][0] += qf.x * k0.x + qf.y * k0.y;
                acc[j][1] += qf.x * k1.x + qf.y * k1.y;
                acc[j][2] += qf.x * k2.x + qf.y * k2.y;
                acc[j][3] += qf.x * k3.x + qf.y * k3.y;
            }
        }

#pragma unroll
        for (int j = 0; j < 5; ++j) {
            int u = 5 * w + j;
            int qi = qism[u];
            float s_l = 0.f;
#pragma unroll
            for (int i = 0; i < 4; ++i) {
                float p = (cbase + kt + 32 * i <= qi) ? __expf(acc[j][i]) : 0.f;
                psm[u * CK + kt + 32 * i] = p;
                s_l += p;
            }
#pragma unroll
            for (int o = 16; o; o >>= 1) s_l += __shfl_xor_sync(0xffffffffu, s_l, o);
            if (kt == 0)
                g_accP[((bh * NC + c) * Uv + u) * 66 + 64] = s_l;
        }
    }
    __syncthreads();

    // ---- PV phase: warp g owns u = 5g+j; lane kt owns d = 2kt, 2kt+1 ----
    int g = w;
    if (qism[5 * g] >= cbase) {
        float fa0[5], fa1[5];
#pragma unroll
        for (int j = 0; j < 5; ++j) { fa0[j] = 0.f; fa1[j] = 0.f; }

#pragma unroll 4
        for (int kk = 0; kk < 32; ++kk) {       // 4 k's per iteration
            unsigned w0 = Vsm[(kk * 4 + 0) * KVS + kt];
            unsigned w1 = Vsm[(kk * 4 + 1) * KVS + kt];
            unsigned w2 = Vsm[(kk * 4 + 2) * KVS + kt];
            unsigned w3 = Vsm[(kk * 4 + 3) * KVS + kt];
            float2 f0 = __bfloat1622float2(*(__nv_bfloat162*)&w0);
            float2 f1 = __bfloat1622float2(*(__nv_bfloat162*)&w1);
            float2 f2 = __bfloat1622float2(*(__nv_bfloat162*)&w2);
            float2 f3 = __bfloat1622float2(*(__nv_bfloat162*)&w3);
#pragma unroll
            for (int j = 0; j < 5; ++j) {
                float4 pf = *(const float4*)&psm[(5 * g + j) * CK + kk * 4];
                fa0[j] += pf.x * f0.x + pf.y * f1.x + pf.z * f2.x + pf.w * f3.x;
                fa1[j] += pf.x * f0.y + pf.y * f1.y + pf.z * f2.y + pf.w * f3.y;
            }
        }
#pragma unroll
        for (int j = 0; j < 5; ++j) {
            int u = 5 * g + j;
            *(float2*)&g_accP[((bh * NC + c) * Uv + u) * 66 + kt * 2] = make_float2(fa0[j], fa1[j]);
        }
    }
}

// ============ K-E: merge partials (causal chunks only), normalize, scatter ============
__global__ void k_attnM(float* __restrict__ out) {
    int bid = blockIdx.x;            // 128 blocks: 4 per bh
    int bh = bid >> 2, q4 = bid & 3;
    int b = bh >> 3, h = bh & 7;
    int t = threadIdx.x;
    for (int e = t; e < 10 * Dv; e += 256) {
        int u = q4 * 10 + (e >> 6), dd = e & 63;
        int qi = g_Mtop[bh * Uv + u];
        int ncu = (qi >> 7) + 1;     // chunks 0..qi/CK inclusive (CK=128)
        float a = 0.f, s = 0.f;
#pragma unroll 4
        for (int c = 0; c < ncu; ++c) {
            const float* base = &g_accP[((bh * NC + c) * Uv + u) * 66];
            a += base[dd];
            s += base[64];
        }
        out[(((b * Lv + qi) * Hv + h) << 6) + dd] = a / s;
    }
}

extern "C" void kernel_launch(void* const* d_in, const int* in_sizes, int n_in,
                              void* d_out, int out_size) {
    const float* Q   = (const float*)d_in[0];
    const float* K   = (const float*)d_in[1];
    const float* V   = (const float*)d_in[2];
    const void*  IDX = d_in[3];
    float* out = (float*)d_out;

    cudaFuncSetAttribute(k_cumAttn, cudaFuncAttributeMaxDynamicSharedMemorySize, SMEM_ATTN);

    k_conv<<<KELEMS / (256 * 8), 256>>>(K, (const int*)IDX);
    k_MbSum<<<MB_BLOCKS + SUM_BLOCKS, 256>>>(Q, IDX, V);
    k_selScan<<<64, 256>>>(Q, K, IDX);
    k_cumAttn<<<ATTN_BLOCKS + CUM_BLOCKS, 256, SMEM_ATTN>>>(Q, K, V, out);
    k_attnM<<<BHv * 4, 256>>>(out);
}

// round 12
// speedup vs baseline: 1.0097x; 1.0097x over previous
#include <cuda_runtime.h>
#include <cuda_bf16.h>
#include <float.h>

// Problem constants
#define Bv 4
#define Lv 2048
#define Hv 8
#define Dv 64
#define SKv 40      // sample_k
#define Uv 40       // top-u
#define NCAND 64
#define BHv 32
#define NCH 32      // cumsum chunks (64 rows each)
#define CROWS 64
#define CK 128      // attention key-chunk size
#define NC 16       // Lv / CK
#define SCALEF 0.125f
#define KELEMS (Bv * Lv * Hv * Dv)

#define MB_BLOCKS 8192
#define SUM_BLOCKS 256
#define ATTN_BLOCKS (BHv * NC)   // 512
#define CUM_BLOCKS 256

// -------- scratch --------
__device__ float        g_M[BHv * Lv];
__device__ int          g_Mtop[BHv * Uv];      // sorted by qi DESCENDING
__device__ float        g_part[BHv * NCH * Dv];
__device__ float        g_accP[BHv * NC * Uv * 66];
__device__ __nv_bfloat16 g_Kbf[KELEMS];
__device__ int          g_is64;

// ============ K-A: bf16 K shadow + index dtype detect ============
__global__ void k_conv(const float* __restrict__ Kt, const int* __restrict__ idx32) {
    if (blockIdx.x == 0 && threadIdx.x < 32) {
        int lane = threadIdx.x;
        int bad = 0;
        for (int j = lane; j < 64; j += 32)
            bad |= (idx32[2 * j + 1] != 0);
        unsigned any = __ballot_sync(0xffffffffu, bad);
        if (lane == 0) g_is64 = (any == 0) ? 1 : 0;
    }
    int idx = (blockIdx.x * 256 + threadIdx.x) * 8;
    float4 a = *(const float4*)(Kt + idx);
    float4 b = *(const float4*)(Kt + idx + 4);
    union { __nv_bfloat162 h[4]; uint4 u; } pk;
    pk.h[0] = __float22bfloat162_rn(make_float2(a.x, a.y));
    pk.h[1] = __float22bfloat162_rn(make_float2(a.z, a.w));
    pk.h[2] = __float22bfloat162_rn(make_float2(b.x, b.y));
    pk.h[3] = __float22bfloat162_rn(make_float2(b.z, b.w));
    *(uint4*)(g_Kbf + idx) = pk.u;
}

// ============ K-B: approx M (bf16 gather) ++ V chunk sums ============
__global__ void k_MbSum(const float* __restrict__ Q, const void* __restrict__ idxraw,
                        const float* __restrict__ V) {
    if (blockIdx.x < MB_BLOCKS) {
        int warp = (blockIdx.x * 256 + threadIdx.x) >> 5;
        int i  = warp & (Lv - 1);
        int bh = warp >> 11;
        int b = bh >> 3, h = bh & 7;
        int lane = threadIdx.x & 31;
        int grp = lane >> 3;
        int j   = lane & 7;

        const int is64 = g_is64;
        const long long* i64 = (const long long*)idxraw;
        const int*       i32 = (const int*)idxraw;

        int rows[10];
#pragma unroll
        for (int p = 0; p < 10; ++p) {
            int s = p * 4 + grp;
            rows[p] = is64 ? (int)i64[i * SKv + s] : i32[i * SKv + s];
        }
        uint4 u[10];
#pragma unroll
        for (int p = 0; p < 10; ++p)
            u[p] = *(const uint4*)(g_Kbf + ((((b << 11) + rows[p]) * Hv + h) << 6) + j * 8);

        const float* qr = Q + ((((b << 11) + i) * Hv + h) << 6);
        float4 qa = *(const float4*)(qr + j * 8);
        float4 qb = *(const float4*)(qr + j * 8 + 4);

        float lmax = -FLT_MAX, lsum = 0.f;
#pragma unroll
        for (int p = 0; p < 10; ++p) {
            const __nv_bfloat162* hp = (const __nv_bfloat162*)&u[p];
            float2 k0 = __bfloat1622float2(hp[0]);
            float2 k1 = __bfloat1622float2(hp[1]);
            float2 k2 = __bfloat1622float2(hp[2]);
            float2 k3 = __bfloat1622float2(hp[3]);
            float d = qa.x * k0.x + qa.y * k0.y + qa.z * k1.x + qa.w * k1.y
                    + qb.x * k2.x + qb.y * k2.y + qb.z * k3.x + qb.w * k3.y;
            d += __shfl_xor_sync(0xffffffffu, d, 1);
            d += __shfl_xor_sync(0xffffffffu, d, 2);
            d += __shfl_xor_sync(0xffffffffu, d, 4);
            lmax = fmaxf(lmax, d);
            lsum += d;
        }
        lmax = fmaxf(lmax, __shfl_xor_sync(0xffffffffu, lmax, 8));
        lmax = fmaxf(lmax, __shfl_xor_sync(0xffffffffu, lmax, 16));
        lsum += __shfl_xor_sync(0xffffffffu, lsum, 8);
        lsum += __shfl_xor_sync(0xffffffffu, lsum, 16);
        if (lane == 0)
            g_M[bh * Lv + i] = lmax - lsum * (1.0f / (float)Lv);
    } else {
        int bid = blockIdx.x - MB_BLOCKS;
        int bh = bid >> 3, cg = bid & 7;
        int b = bh >> 3, h = bh & 7;
        int sub = threadIdx.x >> 6, d = threadIdx.x & 63;
        int chunk = cg * 4 + sub;
        int base = (((b * Lv + chunk * CROWS) * Hv + h) << 6) + d;
        const int stride = Hv * Dv;
        float run = 0.f;
        for (int r0 = 0; r0 < CROWS; r0 += 8) {
            float v[8];
#pragma unroll
            for (int q = 0; q < 8; ++q) v[q] = V[base + (r0 + q) * stride];
#pragma unroll
            for (int q = 0; q < 8; ++q) run += v[q];
        }
        g_part[(bh * NCH + chunk) * Dv + d] = run;
    }
}

// ============ K-C: sel64 -> rescore -> top40 (sorted by qi desc) ++ chunk scan ============
__device__ __forceinline__ unsigned f2u_mono(float f) {
    unsigned u = __float_as_uint(f);
    return (u & 0x80000000u) ? ~u : (u | 0x80000000u);
}

__global__ void k_selScan(const float* __restrict__ Q, const float* __restrict__ Kt,
                          const void* __restrict__ idxraw) {
    __shared__ unsigned keys[Lv];
    __shared__ int hist[256];
    __shared__ int cand_sm[NCAND];
    __shared__ float mex_sm[NCAND];
    __shared__ int selqi[NCAND];
    __shared__ int s_pref, s_rem, s_remN, s_cnt, s_eq;

    if (blockIdx.x >= 32) {
        // ---- scanB: exclusive scan of 32 chunk partials, full-MLP ----
        int bh = blockIdx.x - 32;
        int d = threadIdx.x;
        if (d < 64) {
            float v[NCH];
#pragma unroll
            for (int c = 0; c < NCH; ++c) v[c] = g_part[(bh * NCH + c) * Dv + d];
            float ex = 0.f;
#pragma unroll
            for (int c = 0; c < NCH; ++c) { float tv = v[c]; v[c] = ex; ex += tv; }
#pragma unroll
            for (int c = 0; c < NCH; ++c) g_part[(bh * NCH + c) * Dv + d] = v[c];
        }
        return;
    }

    int bh = blockIdx.x, t = threadIdx.x;
    int b = bh >> 3, h = bh & 7;

    for (int e = t; e < Lv; e += 256)
        keys[e] = f2u_mono(g_M[bh * Lv + e]);
    if (t == 0) { s_pref = 0; s_rem = NCAND; s_cnt = 0; s_eq = 0; }
    __syncthreads();

    unsigned pmask = 0;
#pragma unroll
    for (int pass = 0; pass < 4; ++pass) {
        int shift = 24 - pass * 8;
        hist[t] = 0;
        __syncthreads();
        unsigned pref = (unsigned)s_pref;
        for (int e = t; e < Lv; e += 256) {
            unsigned k = keys[e];
            if ((k & pmask) == pref)
                atomicAdd(&hist[(k >> shift) & 255], 1);
        }
        __syncthreads();
        if (t < 32) {
            int lane = t;
            int h8[8]; int sl = 0;
#pragma unroll
            for (int bb = 0; bb < 8; ++bb) { h8[bb] = hist[lane * 8 + bb]; sl += h8[bb]; }
            int suf = sl;
#pragma unroll
            for (int o = 1; o < 32; o <<= 1) {
                int v = __shfl_down_sync(0xffffffffu, suf, o);
                if (lane + o < 32) suf += v;
            }
            int above = suf - sl;
            int rem = s_rem;
            __syncwarp();
            int run = 0;
#pragma unroll
            for (int bb = 7; bb >= 0; --bb) {
                run += h8[bb];
                int S = above + run;
                if (S >= rem && S - h8[bb] < rem) {
                    s_pref = (int)(pref | ((unsigned)(lane * 8 + bb) << shift));
                    s_remN = rem - (S - h8[bb]);
                }
            }
        }
        __syncthreads();
        if (t == 0) s_rem = s_remN;
        pmask |= (255u << shift);
        __syncthreads();
    }
    unsigned T = (unsigned)s_pref;
    int ceq = s_rem;
    for (int e = t; e < Lv; e += 256) {
        unsigned k = keys[e];
        if (k > T) {
            int pos = atomicAdd(&s_cnt, 1);
            cand_sm[pos] = e;
        } else if (k == T) {
            int p = atomicAdd(&s_eq, 1);
            if (p < ceq) {
                int pos = atomicAdd(&s_cnt, 1);
                cand_sm[pos] = e;
            }
        }
    }
    __syncthreads();

    // ---- exact fp32 rescore: 8 warps x 8 rounds ----
    {
        int w = t >> 5, lane = t & 31;
        int grp = lane >> 3, j = lane & 7;
        const int is64 = g_is64;
        const long long* i64 = (const long long*)idxraw;
        const int*       i32 = (const int*)idxraw;
#pragma unroll 1
        for (int r = 0; r < 8; ++r) {
            int c = r * 8 + w;
            int i = cand_sm[c];
            int rows[10];
#pragma unroll
            for (int p = 0; p < 10; ++p) {
                int s = p * 4 + grp;
                rows[p] = is64 ? (int)i64[i * SKv + s] : i32[i * SKv + s];
            }
            float4 kv[10][2];
#pragma unroll
            for (int p = 0; p < 10; ++p) {
                const float* kr = Kt + ((((b << 11) + rows[p]) * Hv + h) << 6) + j * 8;
                kv[p][0] = *(const float4*)(kr);
                kv[p][1] = *(const float4*)(kr + 4);
            }
            const float* qr = Q + ((((b << 11) + i) * Hv + h) << 6);
            float4 qa = *(const float4*)(qr + j * 8);
            float4 qb = *(const float4*)(qr + j * 8 + 4);

            float lmax = -FLT_MAX, lsum = 0.f;
#pragma unroll
            for (int p = 0; p < 10; ++p) {
                float4 ka = kv[p][0], kb = kv[p][1];
                float d = qa.x * ka.x + qa.y * ka.y + qa.z * ka.z + qa.w * ka.w
                        + qb.x * kb.x + qb.y * kb.y + qb.z * kb.z + qb.w * kb.w;
                d += __shfl_xor_sync(0xffffffffu, d, 1);
                d += __shfl_xor_sync(0xffffffffu, d, 2);
                d += __shfl_xor_sync(0xffffffffu, d, 4);
                lmax = fmaxf(lmax, d);
                lsum += d;
            }
            lmax = fmaxf(lmax, __shfl_xor_sync(0xffffffffu, lmax, 8));
            lmax = fmaxf(lmax, __shfl_xor_sync(0xffffffffu, lmax, 16));
            lsum += __shfl_xor_sync(0xffffffffu, lsum, 8);
            lsum += __shfl_xor_sync(0xffffffffu, lsum, 16);
            if (lane == 0)
                mex_sm[c] = lmax - lsum * (1.0f / (float)Lv);
        }
    }
    __syncthreads();

    // ---- top-40 set by rank counting, ordered by qi DESC ----
    if (t < NCAND) {
        float mv = mex_sm[t];
        int   ci = cand_sm[t];
        int rank = 0;
#pragma unroll
        for (int jj = 0; jj < NCAND; ++jj) {
            float ov = mex_sm[jj];
            int   oi = cand_sm[jj];
            rank += (ov > mv || (ov == mv && oi < ci)) ? 1 : 0;
        }
        selqi[t] = (rank < Uv) ? ci : -1;
    }
    __syncthreads();
    if (t < NCAND && selqi[t] >= 0) {
        int ci = selqi[t];
        int pos = 0;
#pragma unroll
        for (int jj = 0; jj < NCAND; ++jj)
            pos += (selqi[jj] > ci) ? 1 : 0;    // larger qi first
        g_Mtop[bh * Uv + pos] = ci;
    }
}

// ============ K-D: [0,512): causal attention, bf16 K/V smem (63KB -> 3 blocks/SM);
//              [512,768): cumsum writer ============
// smem word layout (uint32 units): K[128][33] | V[128][33] | q f32[40][64] | p f32[40][128] | qi[40]
#define KVS 33                    // row stride in bf16x2 words (bank = (row+col)%32)
#define OFF_V  (CK * KVS)         // 4224
#define OFF_Q  (OFF_V + CK * KVS) // 8448
#define OFF_P  (OFF_Q + Uv * 64)  // 11008
#define OFF_QI (OFF_P + Uv * CK)  // 16128
#define SMEM_ATTN ((OFF_QI + Uv) * 4)   // 64672 B

__global__ void k_cumAttn(const float* __restrict__ Q, const float* __restrict__ Kt,
                          const float* __restrict__ Vt, float* __restrict__ out) {
    if (blockIdx.x >= ATTN_BLOCKS) {
        // ---- cum2: cumsum with chunk offset ----
        int bid = blockIdx.x - ATTN_BLOCKS;
        int bh = bid >> 3, cg = bid & 7;
        int b = bh >> 3, h = bh & 7;
        int sub = threadIdx.x >> 6, d = threadIdx.x & 63;
        int chunk = cg * 4 + sub;
        int base = (((b * Lv + chunk * CROWS) * Hv + h) << 6) + d;
        const int stride = Hv * Dv;
        float run = g_part[(bh * NCH + chunk) * Dv + d];
        for (int r0 = 0; r0 < CROWS; r0 += 8) {
            float v[8];
#pragma unroll
            for (int q = 0; q < 8; ++q) v[q] = Vt[base + (r0 + q) * stride];
#pragma unroll
            for (int q = 0; q < 8; ++q) { run += v[q]; out[base + (r0 + q) * stride] = run; }
        }
        return;
    }

    extern __shared__ unsigned smw[];
    unsigned* Ksm = smw;
    unsigned* Vsm = smw + OFF_V;
    float*    qsm = (float*)(smw + OFF_Q);
    float*    psm = (float*)(smw + OFF_P);
    int*      qism = (int*)(smw + OFF_QI);

    int bid = blockIdx.x;
    int bh = bid >> 4, c = bid & 15;
    int b = bh >> 3, h = bh & 7;
    int t = threadIdx.x;
    int cbase = c * CK;

    if (t < Uv) qism[t] = g_Mtop[bh * Uv + t];
    int n_act = __syncthreads_count(t < Uv && qism[t] >= cbase);
    if (n_act == 0) return;

    // stage K/V as bf16x2 rows (stride 33 words)
    const int kbase = ((b * Lv + cbase) * Hv + h) << 6;
    for (int e = t; e < CK * 16; e += 256) {
        int r = e >> 4, d4 = (e & 15) * 4;
        float4 kv = *(const float4*)(Kt + kbase + r * (Hv * Dv) + d4);
        __nv_bfloat162 ka = __float22bfloat162_rn(make_float2(kv.x, kv.y));
        __nv_bfloat162 kb = __float22bfloat162_rn(make_float2(kv.z, kv.w));
        Ksm[r * KVS + (d4 >> 1)]     = *(unsigned*)&ka;
        Ksm[r * KVS + (d4 >> 1) + 1] = *(unsigned*)&kb;
        float4 vv = *(const float4*)(Vt + kbase + r * (Hv * Dv) + d4);
        __nv_bfloat162 va = __float22bfloat162_rn(make_float2(vv.x, vv.y));
        __nv_bfloat162 vb = __float22bfloat162_rn(make_float2(vv.z, vv.w));
        Vsm[r * KVS + (d4 >> 1)]     = *(unsigned*)&va;
        Vsm[r * KVS + (d4 >> 1) + 1] = *(unsigned*)&vb;
    }
    for (int e = t; e < Uv * 16; e += 256) {
        int u = e >> 4, d4 = (e & 15) * 4;
        int qi = qism[u];
        float4 qv = *(const float4*)(Q + (((b * Lv + qi) * Hv + h) << 6) + d4);
        qv.x *= SCALEF; qv.y *= SCALEF; qv.z *= SCALEF; qv.w *= SCALEF;
        *(float4*)&qsm[u * 64 + d4] = qv;
    }
    __syncthreads();

    int w = t >> 5, kt = t & 31;

    // ---- score phase: warp w owns u = 5w+j; lanes own k = kt + 32i (4 k's) ----
    if (qism[5 * w] >= cbase) {
        float acc[5][4];
#pragma unroll
        for (int j = 0; j < 5; ++j)
#pragma unroll
            for (int i = 0; i < 4; ++i) acc[j][i] = 0.f;

#pragma unroll 4
        for (int dd2 = 0; dd2 < 32; ++dd2) {    // 2 d's per iteration
            unsigned w0 = Ksm[(kt     ) * KVS + dd2];
            unsigned w1 = Ksm[(kt + 32) * KVS + dd2];
            unsigned w2 = Ksm[(kt + 64) * KVS + dd2];
            unsigned w3 = Ksm[(kt + 96) * KVS + dd2];
            float2 k0 = __bfloat1622float2(*(__nv_bfloat162*)&w0);
            float2 k1 = __bfloat1622float2(*(__nv_bfloat162*)&w1);
            float2 k2 = __bfloat1622float2(*(__nv_bfloat162*)&w2);
            float2 k3 = __bfloat1622float2(*(__nv_bfloat162*)&w3);
#pragma unroll
            for (int j = 0; j < 5; ++j) {
                float2 qf = *(const float2*)&qsm[(5 * w + j) * 64 + dd2 * 2];
                acc[j][0] += qf.x * k0.x + qf.y * k0.y;
                acc[j][1] += qf.x * k1.x + qf.y * k1.y;
                acc[j][2] += qf.x * k2.x + qf.y * k2.y;
                acc[j][3] += qf.x * k3.x + qf.y * k3.y;
            }
        }

#pragma unroll
        for (int j = 0; j < 5; ++j) {
            int u = 5 * w + j;
            int qi = qism[u];
            float s_l = 0.f;
#pragma unroll
            for (int i = 0; i < 4; ++i) {
                float p = (cbase + kt + 32 * i <= qi) ? __expf(acc[j][i]) : 0.f;
                psm[u * CK + kt + 32 * i] = p;
                s_l += p;
            }
#pragma unroll
            for (int o = 16; o; o >>= 1) s_l += __shfl_xor_sync(0xffffffffu, s_l, o);
            if (kt == 0)
                g_accP[((bh * NC + c) * Uv + u) * 66 + 64] = s_l;
        }
    }
    __syncthreads();

    // ---- PV phase: warp g owns u = 5g+j; lane kt owns d = 2kt, 2kt+1 ----
    int g = w;
    if (qism[5 * g] >= cbase) {
        float fa0[5], fa1[5];
#pragma unroll
        for (int j = 0; j < 5; ++j) { fa0[j] = 0.f; fa1[j] = 0.f; }

#pragma unroll 4
        for (int kk = 0; kk < 32; ++kk) {       // 4 k's per iteration
            unsigned w0 = Vsm[(kk * 4 + 0) * KVS + kt];
            unsigned w1 = Vsm[(kk * 4 + 1) * KVS + kt];
            unsigned w2 = Vsm[(kk * 4 + 2) * KVS + kt];
            unsigned w3 = Vsm[(kk * 4 + 3) * KVS + kt];
            float2 f0 = __bfloat1622float2(*(__nv_bfloat162*)&w0);
            float2 f1 = __bfloat1622float2(*(__nv_bfloat162*)&w1);
            float2 f2 = __bfloat1622float2(*(__nv_bfloat162*)&w2);
            float2 f3 = __bfloat1622float2(*(__nv_bfloat162*)&w3);
#pragma unroll
            for (int j = 0; j < 5; ++j) {
                float4 pf = *(const float4*)&psm[(5 * g + j) * CK + kk * 4];
                fa0[j] += pf.x * f0.x + pf.y * f1.x + pf.z * f2.x + pf.w * f3.x;
                fa1[j] += pf.x * f0.y + pf.y * f1.y + pf.z * f2.y + pf.w * f3.y;
            }
        }
#pragma unroll
        for (int j = 0; j < 5; ++j) {
            int u = 5 * g + j;
            *(float2*)&g_accP[((bh * NC + c) * Uv + u) * 66 + kt * 2] = make_float2(fa0[j], fa1[j]);
        }
    }
}

// ============ K-E: merge partials (causal chunks only), normalize, scatter ============
__global__ void k_attnM(float* __restrict__ out) {
    int bid = blockIdx.x;            // 128 blocks: 4 per bh
    int bh = bid >> 2, q4 = bid & 3;
    int b = bh >> 3, h = bh & 7;
    int t = threadIdx.x;
    for (int e = t; e < 10 * Dv; e += 256) {
        int u = q4 * 10 + (e >> 6), dd = e & 63;
        int qi = g_Mtop[bh * Uv + u];
        int ncu = (qi >> 7) + 1;     // chunks 0..qi/CK inclusive (CK=128)
        float a = 0.f, s = 0.f;
#pragma unroll 4
        for (int c = 0; c < ncu; ++c) {
            const float* base = &g_accP[((bh * NC + c) * Uv + u) * 66];
            a += base[dd];
            s += base[64];
        }
        out[(((b * Lv + qi) * Hv + h) << 6) + dd] = a / s;
    }
}

extern "C" void kernel_launch(void* const* d_in, const int* in_sizes, int n_in,
                              void* d_out, int out_size) {
    const float* Q   = (const float*)d_in[0];
    const float* K   = (const float*)d_in[1];
    const float* V   = (const float*)d_in[2];
    const void*  IDX = d_in[3];
    float* out = (float*)d_out;

    cudaFuncSetAttribute(k_cumAttn, cudaFuncAttributeMaxDynamicSharedMemorySize, SMEM_ATTN);

    k_conv<<<KELEMS / (256 * 8), 256>>>(K, (const int*)IDX);
    k_MbSum<<<MB_BLOCKS + SUM_BLOCKS, 256>>>(Q, IDX, V);
    k_selScan<<<64, 256>>>(Q, K, IDX);
    k_cumAttn<<<ATTN_BLOCKS + CUM_BLOCKS, 256, SMEM_ATTN>>>(Q, K, V, out);
    k_attnM<<<BHv * 4, 256>>>(out);
}

// round 13
// speedup vs baseline: 1.0362x; 1.0262x over previous
#include <cuda_runtime.h>
#include <cuda_bf16.h>
#include <float.h>

// Problem constants
#define Bv 4
#define Lv 2048
#define Hv 8
#define Dv 64
#define SKv 40      // sample_k
#define Uv 40       // top-u
#define NCAND 64
#define BHv 32
#define NCH 32      // cumsum chunks (64 rows each)
#define CROWS 64
#define CK 128      // attention key-chunk size
#define NC 16       // Lv / CK
#define SCALEF 0.125f
#define KELEMS (Bv * Lv * Hv * Dv)

#define MB_BLOCKS 8192
#define SUM_BLOCKS 256
#define ATTN_BLOCKS (BHv * NC)   // 512
#define CUM_BLOCKS 128           // 8 chunks per block
#define ATTN_THREADS 640         // 20 warps: 2 queries per warp

// -------- scratch --------
__device__ float        g_M[BHv * Lv];
__device__ int          g_Mtop[BHv * Uv];      // sorted by qi DESCENDING
__device__ float        g_part[BHv * NCH * Dv];
__device__ float        g_accP[BHv * NC * Uv * 66];
__device__ __nv_bfloat16 g_Kbf[KELEMS];
__device__ int          g_is64;

// ============ K-A: bf16 K shadow + index dtype detect ============
__global__ void k_conv(const float* __restrict__ Kt, const int* __restrict__ idx32) {
    if (blockIdx.x == 0 && threadIdx.x < 32) {
        int lane = threadIdx.x;
        int bad = 0;
        for (int j = lane; j < 64; j += 32)
            bad |= (idx32[2 * j + 1] != 0);
        unsigned any = __ballot_sync(0xffffffffu, bad);
        if (lane == 0) g_is64 = (any == 0) ? 1 : 0;
    }
    int idx = (blockIdx.x * 256 + threadIdx.x) * 8;
    float4 a = *(const float4*)(Kt + idx);
    float4 b = *(const float4*)(Kt + idx + 4);
    union { __nv_bfloat162 h[4]; uint4 u; } pk;
    pk.h[0] = __float22bfloat162_rn(make_float2(a.x, a.y));
    pk.h[1] = __float22bfloat162_rn(make_float2(a.z, a.w));
    pk.h[2] = __float22bfloat162_rn(make_float2(b.x, b.y));
    pk.h[3] = __float22bfloat162_rn(make_float2(b.z, b.w));
    *(uint4*)(g_Kbf + idx) = pk.u;
}

// ============ K-B: approx M (bf16 gather) ++ V chunk sums ============
__global__ void k_MbSum(const float* __restrict__ Q, const void* __restrict__ idxraw,
                        const float* __restrict__ V) {
    if (blockIdx.x < MB_BLOCKS) {
        int warp = (blockIdx.x * 256 + threadIdx.x) >> 5;
        int i  = warp & (Lv - 1);
        int bh = warp >> 11;
        int b = bh >> 3, h = bh & 7;
        int lane = threadIdx.x & 31;
        int grp = lane >> 3;
        int j   = lane & 7;

        const int is64 = g_is64;
        const long long* i64 = (const long long*)idxraw;
        const int*       i32 = (const int*)idxraw;

        int rows[10];
#pragma unroll
        for (int p = 0; p < 10; ++p) {
            int s = p * 4 + grp;
            rows[p] = is64 ? (int)i64[i * SKv + s] : i32[i * SKv + s];
        }
        uint4 u[10];
#pragma unroll
        for (int p = 0; p < 10; ++p)
            u[p] = *(const uint4*)(g_Kbf + ((((b << 11) + rows[p]) * Hv + h) << 6) + j * 8);

        const float* qr = Q + ((((b << 11) + i) * Hv + h) << 6);
        float4 qa = *(const float4*)(qr + j * 8);
        float4 qb = *(const float4*)(qr + j * 8 + 4);

        float lmax = -FLT_MAX, lsum = 0.f;
#pragma unroll
        for (int p = 0; p < 10; ++p) {
            const __nv_bfloat162* hp = (const __nv_bfloat162*)&u[p];
            float2 k0 = __bfloat1622float2(hp[0]);
            float2 k1 = __bfloat1622float2(hp[1]);
            float2 k2 = __bfloat1622float2(hp[2]);
            float2 k3 = __bfloat1622float2(hp[3]);
            float d = qa.x * k0.x + qa.y * k0.y + qa.z * k1.x + qa.w * k1.y
                    + qb.x * k2.x + qb.y * k2.y + qb.z * k3.x + qb.w * k3.y;
            d += __shfl_xor_sync(0xffffffffu, d, 1);
            d += __shfl_xor_sync(0xffffffffu, d, 2);
            d += __shfl_xor_sync(0xffffffffu, d, 4);
            lmax = fmaxf(lmax, d);
            lsum += d;
        }
        lmax = fmaxf(lmax, __shfl_xor_sync(0xffffffffu, lmax, 8));
        lmax = fmaxf(lmax, __shfl_xor_sync(0xffffffffu, lmax, 16));
        lsum += __shfl_xor_sync(0xffffffffu, lsum, 8);
        lsum += __shfl_xor_sync(0xffffffffu, lsum, 16);
        if (lane == 0)
            g_M[bh * Lv + i] = lmax - lsum * (1.0f / (float)Lv);
    } else {
        int bid = blockIdx.x - MB_BLOCKS;
        int bh = bid >> 3, cg = bid & 7;
        int b = bh >> 3, h = bh & 7;
        int sub = threadIdx.x >> 6, d = threadIdx.x & 63;
        int chunk = cg * 4 + sub;
        int base = (((b * Lv + chunk * CROWS) * Hv + h) << 6) + d;
        const int stride = Hv * Dv;
        float run = 0.f;
        for (int r0 = 0; r0 < CROWS; r0 += 8) {
            float v[8];
#pragma unroll
            for (int q = 0; q < 8; ++q) v[q] = V[base + (r0 + q) * stride];
#pragma unroll
            for (int q = 0; q < 8; ++q) run += v[q];
        }
        g_part[(bh * NCH + chunk) * Dv + d] = run;
    }
}

// ============ K-C: sel64 -> rescore -> top40 (sorted by qi desc) ++ chunk scan ============
__device__ __forceinline__ unsigned f2u_mono(float f) {
    unsigned u = __float_as_uint(f);
    return (u & 0x80000000u) ? ~u : (u | 0x80000000u);
}

__global__ void k_selScan(const float* __restrict__ Q, const float* __restrict__ Kt,
                          const void* __restrict__ idxraw) {
    __shared__ unsigned keys[Lv];
    __shared__ int hist[256];
    __shared__ int cand_sm[NCAND];
    __shared__ float mex_sm[NCAND];
    __shared__ int selqi[NCAND];
    __shared__ int s_pref, s_rem, s_remN, s_cnt, s_eq;

    if (blockIdx.x >= 32) {
        // ---- scanB: exclusive scan of 32 chunk partials, full-MLP ----
        int bh = blockIdx.x - 32;
        int d = threadIdx.x;
        if (d < 64) {
            float v[NCH];
#pragma unroll
            for (int c = 0; c < NCH; ++c) v[c] = g_part[(bh * NCH + c) * Dv + d];
            float ex = 0.f;
#pragma unroll
            for (int c = 0; c < NCH; ++c) { float tv = v[c]; v[c] = ex; ex += tv; }
#pragma unroll
            for (int c = 0; c < NCH; ++c) g_part[(bh * NCH + c) * Dv + d] = v[c];
        }
        return;
    }

    int bh = blockIdx.x, t = threadIdx.x;
    int b = bh >> 3, h = bh & 7;

    for (int e = t; e < Lv; e += 256)
        keys[e] = f2u_mono(g_M[bh * Lv + e]);
    if (t == 0) { s_pref = 0; s_rem = NCAND; s_cnt = 0; s_eq = 0; }
    __syncthreads();

    unsigned pmask = 0;
#pragma unroll
    for (int pass = 0; pass < 4; ++pass) {
        int shift = 24 - pass * 8;
        hist[t] = 0;
        __syncthreads();
        unsigned pref = (unsigned)s_pref;
        for (int e = t; e < Lv; e += 256) {
            unsigned k = keys[e];
            if ((k & pmask) == pref)
                atomicAdd(&hist[(k >> shift) & 255], 1);
        }
        __syncthreads();
        if (t < 32) {
            int lane = t;
            int h8[8]; int sl = 0;
#pragma unroll
            for (int bb = 0; bb < 8; ++bb) { h8[bb] = hist[lane * 8 + bb]; sl += h8[bb]; }
            int suf = sl;
#pragma unroll
            for (int o = 1; o < 32; o <<= 1) {
                int v = __shfl_down_sync(0xffffffffu, suf, o);
                if (lane + o < 32) suf += v;
            }
            int above = suf - sl;
            int rem = s_rem;
            __syncwarp();
            int run = 0;
#pragma unroll
            for (int bb = 7; bb >= 0; --bb) {
                run += h8[bb];
                int S = above + run;
                if (S >= rem && S - h8[bb] < rem) {
                    s_pref = (int)(pref | ((unsigned)(lane * 8 + bb) << shift));
                    s_remN = rem - (S - h8[bb]);
                }
            }
        }
        __syncthreads();
        if (t == 0) s_rem = s_remN;
        pmask |= (255u << shift);
        __syncthreads();
    }
    unsigned T = (unsigned)s_pref;
    int ceq = s_rem;
    for (int e = t; e < Lv; e += 256) {
        unsigned k = keys[e];
        if (k > T) {
            int pos = atomicAdd(&s_cnt, 1);
            cand_sm[pos] = e;
        } else if (k == T) {
            int p = atomicAdd(&s_eq, 1);
            if (p < ceq) {
                int pos = atomicAdd(&s_cnt, 1);
                cand_sm[pos] = e;
            }
        }
    }
    __syncthreads();

    // ---- exact fp32 rescore: 8 warps x 8 rounds ----
    {
        int w = t >> 5, lane = t & 31;
        int grp = lane >> 3, j = lane & 7;
        const int is64 = g_is64;
        const long long* i64 = (const long long*)idxraw;
        const int*       i32 = (const int*)idxraw;
#pragma unroll 1
        for (int r = 0; r < 8; ++r) {
            int c = r * 8 + w;
            int i = cand_sm[c];
            int rows[10];
#pragma unroll
            for (int p = 0; p < 10; ++p) {
                int s = p * 4 + grp;
                rows[p] = is64 ? (int)i64[i * SKv + s] : i32[i * SKv + s];
            }
            float4 kv[10][2];
#pragma unroll
            for (int p = 0; p < 10; ++p) {
                const float* kr = Kt + ((((b << 11) + rows[p]) * Hv + h) << 6) + j * 8;
                kv[p][0] = *(const float4*)(kr);
                kv[p][1] = *(const float4*)(kr + 4);
            }
            const float* qr = Q + ((((b << 11) + i) * Hv + h) << 6);
            float4 qa = *(const float4*)(qr + j * 8);
            float4 qb = *(const float4*)(qr + j * 8 + 4);

            float lmax = -FLT_MAX, lsum = 0.f;
#pragma unroll
            for (int p = 0; p < 10; ++p) {
                float4 ka = kv[p][0], kb = kv[p][1];
                float d = qa.x * ka.x + qa.y * ka.y + qa.z * ka.z + qa.w * ka.w
                        + qb.x * kb.x + qb.y * kb.y + qb.z * kb.z + qb.w * kb.w;
                d += __shfl_xor_sync(0xffffffffu, d, 1);
                d += __shfl_xor_sync(0xffffffffu, d, 2);
                d += __shfl_xor_sync(0xffffffffu, d, 4);
                lmax = fmaxf(lmax, d);
                lsum += d;
            }
            lmax = fmaxf(lmax, __shfl_xor_sync(0xffffffffu, lmax, 8));
            lmax = fmaxf(lmax, __shfl_xor_sync(0xffffffffu, lmax, 16));
            lsum += __shfl_xor_sync(0xffffffffu, lsum, 8);
            lsum += __shfl_xor_sync(0xffffffffu, lsum, 16);
            if (lane == 0)
                mex_sm[c] = lmax - lsum * (1.0f / (float)Lv);
        }
    }
    __syncthreads();

    // ---- top-40 set by rank counting, ordered by qi DESC ----
    if (t < NCAND) {
        float mv = mex_sm[t];
        int   ci = cand_sm[t];
        int rank = 0;
#pragma unroll
        for (int jj = 0; jj < NCAND; ++jj) {
            float ov = mex_sm[jj];
            int   oi = cand_sm[jj];
            rank += (ov > mv || (ov == mv && oi < ci)) ? 1 : 0;
        }
        selqi[t] = (rank < Uv) ? ci : -1;
    }
    __syncthreads();
    if (t < NCAND && selqi[t] >= 0) {
        int ci = selqi[t];
        int pos = 0;
#pragma unroll
        for (int jj = 0; jj < NCAND; ++jj)
            pos += (selqi[jj] > ci) ? 1 : 0;    // larger qi first
        g_Mtop[bh * Uv + pos] = ci;
    }
}

// ============ K-D: [0,512): causal attention (CK=128, fp32 smem, 20 warps x 2u);
//              [512,640): cumsum writer (8 chunks per block) ============
#define KS4 68   // K row stride (float4-aligned, conflict-free LDS.128)
#define VS2 66   // V row stride (float2, conflict-free LDS.64)
#define OFF_V  (CK * KS4)
#define OFF_Q  (OFF_V + CK * VS2)
#define OFF_P  (OFF_Q + Uv * 64)
#define OFF_QI (OFF_P + Uv * CK)
#define SMEM_ATTN ((OFF_QI + Uv) * 4)

__global__ void k_cumAttn(const float* __restrict__ Q, const float* __restrict__ Kt,
                          const float* __restrict__ Vt, float* __restrict__ out) {
    if (blockIdx.x >= ATTN_BLOCKS) {
        // ---- cum2: cumsum with chunk offset; 8 chunks per block (subs 0..7 of 10) ----
        int bid = blockIdx.x - ATTN_BLOCKS;    // 128 blocks
        int bh = bid >> 2, cg = bid & 3;
        int b = bh >> 3, h = bh & 7;
        int sub = threadIdx.x >> 6, d = threadIdx.x & 63;
        if (sub >= 8) return;
        int chunk = cg * 8 + sub;
        int base = (((b * Lv + chunk * CROWS) * Hv + h) << 6) + d;
        const int stride = Hv * Dv;
        float run = g_part[(bh * NCH + chunk) * Dv + d];
        for (int r0 = 0; r0 < CROWS; r0 += 8) {
            float v[8];
#pragma unroll
            for (int q = 0; q < 8; ++q) v[q] = Vt[base + (r0 + q) * stride];
#pragma unroll
            for (int q = 0; q < 8; ++q) { run += v[q]; out[base + (r0 + q) * stride] = run; }
        }
        return;
    }

    extern __shared__ float sm[];
    float* Ksm = sm;
    float* Vsm = sm + OFF_V;
    float* qsm = sm + OFF_Q;
    float* psm = sm + OFF_P;
    int*   qism = (int*)(sm + OFF_QI);

    int bid = blockIdx.x;
    int bh = bid >> 4, c = bid & 15;
    int b = bh >> 3, h = bh & 7;
    int t = threadIdx.x;
    int cbase = c * CK;

    if (t < Uv) qism[t] = g_Mtop[bh * Uv + t];
    int n_act = __syncthreads_count(t < Uv && qism[t] >= cbase);
    if (n_act == 0) return;   // uniform

    // stage K (float4, stride 68) and V (stride 66)
    const int kbase = ((b * Lv + cbase) * Hv + h) << 6;
    for (int e = t; e < CK * 16; e += ATTN_THREADS) {
        int r = e >> 4, d4 = (e & 15) * 4;
        *(float4*)&Ksm[r * KS4 + d4] = *(const float4*)(Kt + kbase + r * (Hv * Dv) + d4);
        float4 vv = *(const float4*)(Vt + kbase + r * (Hv * Dv) + d4);
        Vsm[r * VS2 + d4 + 0] = vv.x; Vsm[r * VS2 + d4 + 1] = vv.y;
        Vsm[r * VS2 + d4 + 2] = vv.z; Vsm[r * VS2 + d4 + 3] = vv.w;
    }
    for (int e = t; e < Uv * 16; e += ATTN_THREADS) {
        int u = e >> 4, d4 = (e & 15) * 4;
        int qi = qism[u];
        float4 qv = *(const float4*)(Q + (((b * Lv + qi) * Hv + h) << 6) + d4);
        qv.x *= SCALEF; qv.y *= SCALEF; qv.z *= SCALEF; qv.w *= SCALEF;
        *(float4*)&qsm[u * 64 + d4] = qv;
    }
    __syncthreads();

    int w = t >> 5, kt = t & 31;   // 20 warps; warp w owns u = 2w, 2w+1

    // ---- score phase: fixed trips, warp-uniform skip ----
    if (qism[2 * w] >= cbase) {
        float acc[2][4];
#pragma unroll
        for (int j = 0; j < 2; ++j)
#pragma unroll
            for (int i = 0; i < 4; ++i) acc[j][i] = 0.f;

#pragma unroll 4
        for (int dd4 = 0; dd4 < 16; ++dd4) {
            float4 k0 = *(const float4*)&Ksm[(kt     ) * KS4 + dd4 * 4];
            float4 k1 = *(const float4*)&Ksm[(kt + 32) * KS4 + dd4 * 4];
            float4 k2 = *(const float4*)&Ksm[(kt + 64) * KS4 + dd4 * 4];
            float4 k3 = *(const float4*)&Ksm[(kt + 96) * KS4 + dd4 * 4];
#pragma unroll
            for (int j = 0; j < 2; ++j) {
                float4 qf = *(const float4*)&qsm[(2 * w + j) * 64 + dd4 * 4];
                acc[j][0] += qf.x * k0.x + qf.y * k0.y + qf.z * k0.z + qf.w * k0.w;
                acc[j][1] += qf.x * k1.x + qf.y * k1.y + qf.z * k1.z + qf.w * k1.w;
                acc[j][2] += qf.x * k2.x + qf.y * k2.y + qf.z * k2.z + qf.w * k2.w;
                acc[j][3] += qf.x * k3.x + qf.y * k3.y + qf.z * k3.z + qf.w * k3.w;
            }
        }

#pragma unroll
        for (int j = 0; j < 2; ++j) {
            int u = 2 * w + j;
            int qi = qism[u];
            float s_l = 0.f;
#pragma unroll
            for (int i = 0; i < 4; ++i) {
                float p = (cbase + kt + 32 * i <= qi) ? __expf(acc[j][i]) : 0.f;
                psm[u * CK + kt + 32 * i] = p;
                s_l += p;
            }
#pragma unroll
            for (int o = 16; o; o >>= 1) s_l += __shfl_xor_sync(0xffffffffu, s_l, o);
            if (kt == 0)
                g_accP[((bh * NC + c) * Uv + u) * 66 + 64] = s_l;
        }
    }
    __syncthreads();

    // ---- PV phase: warp g owns u = 2g, 2g+1; lane kt owns d = 2kt, 2kt+1 ----
    int g = w, d2 = kt * 2;
    if (qism[2 * g] >= cbase) {
        float fa0[2], fa1[2];
#pragma unroll
        for (int j = 0; j < 2; ++j) { fa0[j] = 0.f; fa1[j] = 0.f; }

#pragma unroll 4
        for (int kk = 0; kk < 32; ++kk) {
            float2 v0 = *(const float2*)&Vsm[(kk * 4 + 0) * VS2 + d2];
            float2 v1 = *(const float2*)&Vsm[(kk * 4 + 1) * VS2 + d2];
            float2 v2 = *(const float2*)&Vsm[(kk * 4 + 2) * VS2 + d2];
            float2 v3 = *(const float2*)&Vsm[(kk * 4 + 3) * VS2 + d2];
#pragma unroll
            for (int j = 0; j < 2; ++j) {
                float4 pf = *(const float4*)&psm[(2 * g + j) * CK + kk * 4];
                fa0[j] += pf.x * v0.x + pf.y * v1.x + pf.z * v2.x + pf.w * v3.x;
                fa1[j] += pf.x * v0.y + pf.y * v1.y + pf.z * v2.y + pf.w * v3.y;
            }
        }
#pragma unroll
        for (int j = 0; j < 2; ++j) {
            int u = 2 * g + j;
            *(float2*)&g_accP[((bh * NC + c) * Uv + u) * 66 + d2] = make_float2(fa0[j], fa1[j]);
        }
    }
}

// ============ K-E: merge partials (causal chunks only), normalize, scatter ============
__global__ void k_attnM(float* __restrict__ out) {
    int bid = blockIdx.x;            // 128 blocks: 4 per bh
    int bh = bid >> 2, q4 = bid & 3;
    int b = bh >> 3, h = bh & 7;
    int t = threadIdx.x;
    for (int e = t; e < 10 * Dv; e += 256) {
        int u = q4 * 10 + (e >> 6), dd = e & 63;
        int qi = g_Mtop[bh * Uv + u];
        int ncu = (qi >> 7) + 1;     // chunks 0..qi/CK inclusive (CK=128)
        float a = 0.f, s = 0.f;
#pragma unroll 4
        for (int c = 0; c < ncu; ++c) {
            const float* base = &g_accP[((bh * NC + c) * Uv + u) * 66];
            a += base[dd];
            s += base[64];
        }
        out[(((b * Lv + qi) * Hv + h) << 6) + dd] = a / s;
    }
}

extern "C" void kernel_launch(void* const* d_in, const int* in_sizes, int n_in,
                              void* d_out, int out_size) {
    const float* Q   = (const float*)d_in[0];
    const float* K   = (const float*)d_in[1];
    const float* V   = (const float*)d_in[2];
    const void*  IDX = d_in[3];
    float* out = (float*)d_out;

    cudaFuncSetAttribute(k_cumAttn, cudaFuncAttributeMaxDynamicSharedMemorySize, SMEM_ATTN);

    k_conv<<<KELEMS / (256 * 8), 256>>>(K, (const int*)IDX);
    k_MbSum<<<MB_BLOCKS + SUM_BLOCKS, 256>>>(Q, IDX, V);
    k_selScan<<<64, 256>>>(Q, K, IDX);
    k_cumAttn<<<ATTN_BLOCKS + CUM_BLOCKS, ATTN_THREADS, SMEM_ATTN>>>(Q, K, V, out);
    k_attnM<<<BHv * 4, 256>>>(out);
}

// round 14
// speedup vs baseline: 1.1209x; 1.0818x over previous
#include <cuda_runtime.h>
#include <cuda_bf16.h>
#include <float.h>

// Problem constants
#define Bv 4
#define Lv 2048
#define Hv 8
#define Dv 64
#define SKv 40      // sample_k
#define Uv 40       // top-u
#define NCAND 96    // int8-approx margin (validated exact-equivalent in R10)
#define BHv 32
#define NCH 32      // cumsum chunks (64 rows each)
#define CROWS 64
#define CK 128      // attention key-chunk size
#define NC 16       // Lv / CK
#define SCALEF 0.125f
#define KELEMS (Bv * Lv * Hv * Dv)
#define KSCALE (5.5f / 127.0f)   // global int8 scale for K (N(0,1), clamp 5.5 sigma)
#define KINV   (127.0f / 5.5f)

#define MB_BLOCKS 8192
#define SUM_BLOCKS 256
#define ATTN_BLOCKS (BHv * NC)   // 512
#define CUM_BLOCKS 256

// -------- scratch --------
__device__ float        g_M[BHv * Lv];
__device__ int          g_Mtop[BHv * Uv];      // sorted by qi DESCENDING
__device__ float        g_part[BHv * NCH * Dv];
__device__ float        g_accP[BHv * NC * Uv * 66];
__device__ uint4        g_K8[KELEMS / 16];     // int8 K shadow (64B rows)
__device__ uint4        g_Q8[KELEMS / 16];     // int8 Q shadow (per-row scale)
__device__ float        g_qs[KELEMS / 64];     // Q row scales (amax/127)
__device__ int          g_is64;

// ============ K-A: int8 K+Q shadows + index dtype detect ============
__global__ void k_conv(const float* __restrict__ Kt, const float* __restrict__ Q,
                       const int* __restrict__ idx32) {
    if (blockIdx.x == 0 && threadIdx.x < 32) {
        int lane = threadIdx.x;
        int bad = 0;
        for (int j = lane; j < 64; j += 32)
            bad |= (idx32[2 * j + 1] != 0);
        unsigned any = __ballot_sync(0xffffffffu, bad);
        if (lane == 0) g_is64 = (any == 0) ? 1 : 0;
    }
    int tid = blockIdx.x * 256 + threadIdx.x;
    int idx = tid * 8;

    // ---- K: global-scale int8 ----
    {
        float4 a = *(const float4*)(Kt + idx);
        float4 b = *(const float4*)(Kt + idx + 4);
        float v[8] = {a.x, a.y, a.z, a.w, b.x, b.y, b.z, b.w};
        unsigned w0 = 0, w1 = 0;
#pragma unroll
        for (int e = 0; e < 4; ++e) {
            int q = __float2int_rn(fminf(fmaxf(v[e] * KINV, -127.f), 127.f));
            w0 |= ((unsigned)q & 0xFFu) << (e * 8);
        }
#pragma unroll
        for (int e = 0; e < 4; ++e) {
            int q = __float2int_rn(fminf(fmaxf(v[4 + e] * KINV, -127.f), 127.f));
            w1 |= ((unsigned)q & 0xFFu) << (e * 8);
        }
        ((uint2*)g_K8)[idx >> 3] = make_uint2(w0, w1);
    }

    // ---- Q: per-row (64-elem) scale int8; 8 aligned threads per row ----
    {
        float4 a = *(const float4*)(Q + idx);
        float4 b = *(const float4*)(Q + idx + 4);
        float v[8] = {a.x, a.y, a.z, a.w, b.x, b.y, b.z, b.w};
        float amax = 0.f;
#pragma unroll
        for (int e = 0; e < 8; ++e) amax = fmaxf(amax, fabsf(v[e]));
        amax = fmaxf(amax, __shfl_xor_sync(0xffffffffu, amax, 1));
        amax = fmaxf(amax, __shfl_xor_sync(0xffffffffu, amax, 2));
        amax = fmaxf(amax, __shfl_xor_sync(0xffffffffu, amax, 4));
        float inv = (amax > 0.f) ? (127.f / amax) : 0.f;
        unsigned w0 = 0, w1 = 0;
#pragma unroll
        for (int e = 0; e < 4; ++e) {
            int q = __float2int_rn(fminf(fmaxf(v[e] * inv, -127.f), 127.f));
            w0 |= ((unsigned)q & 0xFFu) << (e * 8);
        }
#pragma unroll
        for (int e = 0; e < 4; ++e) {
            int q = __float2int_rn(fminf(fmaxf(v[4 + e] * inv, -127.f), 127.f));
            w1 |= ((unsigned)q & 0xFFu) << (e * 8);
        }
        ((uint2*)g_Q8)[idx >> 3] = make_uint2(w0, w1);
        if ((threadIdx.x & 7) == 0)
            g_qs[idx >> 6] = amax * (1.f / 127.f);
    }
}

// ============ K-B: approx M (int8 dp4a gather, pre-quantized Q) ++ V chunk sums ============
__global__ void k_MbSum(const void* __restrict__ idxraw, const float* __restrict__ V) {
    if (blockIdx.x < MB_BLOCKS) {
        // one warp per query; 8 groups of 4 lanes; 5 passes of 8 samples
        int warp = (blockIdx.x * 256 + threadIdx.x) >> 5;
        int i  = warp & (Lv - 1);
        int bh = warp >> 11;
        int b = bh >> 3, h = bh & 7;
        int lane = threadIdx.x & 31;
        int grp = lane >> 2;    // 0..7
        int j4  = lane & 3;     // 0..3 (16 int8 each)

        const int is64 = g_is64;
        const long long* i64 = (const long long*)idxraw;
        const int*       i32 = (const int*)idxraw;

        int rows[5];
#pragma unroll
        for (int p = 0; p < 5; ++p) {
            int s = p * 8 + grp;
            rows[p] = is64 ? (int)i64[i * SKv + s] : i32[i * SKv + s];
        }
        // prefetch all 5 gathered 16B chunks (MLP=5) + q word + scale
        uint4 kw[5];
#pragma unroll
        for (int p = 0; p < 5; ++p)
            kw[p] = g_K8[((((b << 11) + rows[p]) * Hv + h) << 2) + j4];
        int qrow = ((b << 11) + i) * Hv + h;
        uint4 qv4 = g_Q8[(qrow << 2) + j4];
        float dscale = g_qs[qrow] * KSCALE;

        float lmax = -FLT_MAX, lsum = 0.f;
#pragma unroll
        for (int p = 0; p < 5; ++p) {
            int di = 0;
            di = __dp4a((int)kw[p].x, (int)qv4.x, di);
            di = __dp4a((int)kw[p].y, (int)qv4.y, di);
            di = __dp4a((int)kw[p].z, (int)qv4.z, di);
            di = __dp4a((int)kw[p].w, (int)qv4.w, di);
            di += __shfl_xor_sync(0xffffffffu, di, 1);
            di += __shfl_xor_sync(0xffffffffu, di, 2);
            float d = (float)di * dscale;
            lmax = fmaxf(lmax, d);
            lsum += d;
        }
        // combine across 8 groups
        lmax = fmaxf(lmax, __shfl_xor_sync(0xffffffffu, lmax, 4));
        lmax = fmaxf(lmax, __shfl_xor_sync(0xffffffffu, lmax, 8));
        lmax = fmaxf(lmax, __shfl_xor_sync(0xffffffffu, lmax, 16));
        lsum += __shfl_xor_sync(0xffffffffu, lsum, 4);
        lsum += __shfl_xor_sync(0xffffffffu, lsum, 8);
        lsum += __shfl_xor_sync(0xffffffffu, lsum, 16);
        if (lane == 0)
            g_M[bh * Lv + i] = lmax - lsum * (1.0f / (float)Lv);
    } else {
        int bid = blockIdx.x - MB_BLOCKS;
        int bh = bid >> 3, cg = bid & 7;
        int b = bh >> 3, h = bh & 7;
        int sub = threadIdx.x >> 6, d = threadIdx.x & 63;
        int chunk = cg * 4 + sub;
        int base = (((b * Lv + chunk * CROWS) * Hv + h) << 6) + d;
        const int stride = Hv * Dv;
        float run = 0.f;
        for (int r0 = 0; r0 < CROWS; r0 += 8) {
            float v[8];
#pragma unroll
            for (int q = 0; q < 8; ++q) v[q] = V[base + (r0 + q) * stride];
#pragma unroll
            for (int q = 0; q < 8; ++q) run += v[q];
        }
        g_part[(bh * NCH + chunk) * Dv + d] = run;
    }
}

// ============ K-C: sel96 -> exact rescore -> top40 (qi desc) ++ chunk scan ============
__device__ __forceinline__ unsigned f2u_mono(float f) {
    unsigned u = __float_as_uint(f);
    return (u & 0x80000000u) ? ~u : (u | 0x80000000u);
}

__global__ void k_selScan(const float* __restrict__ Q, const float* __restrict__ Kt,
                          const void* __restrict__ idxraw) {
    __shared__ unsigned keys[Lv];
    __shared__ int hist[256];
    __shared__ int cand_sm[NCAND];
    __shared__ float mex_sm[NCAND];
    __shared__ int selqi[NCAND];
    __shared__ int s_pref, s_rem, s_remN, s_cnt, s_eq;

    if (blockIdx.x >= 32) {
        // ---- scanB: exclusive scan of 32 chunk partials, full-MLP ----
        int bh = blockIdx.x - 32;
        int d = threadIdx.x;
        if (d < 64) {
            float v[NCH];
#pragma unroll
            for (int c = 0; c < NCH; ++c) v[c] = g_part[(bh * NCH + c) * Dv + d];
            float ex = 0.f;
#pragma unroll
            for (int c = 0; c < NCH; ++c) { float tv = v[c]; v[c] = ex; ex += tv; }
#pragma unroll
            for (int c = 0; c < NCH; ++c) g_part[(bh * NCH + c) * Dv + d] = v[c];
        }
        return;
    }

    int bh = blockIdx.x, t = threadIdx.x;
    int b = bh >> 3, h = bh & 7;

    for (int e = t; e < Lv; e += 256)
        keys[e] = f2u_mono(g_M[bh * Lv + e]);
    if (t == 0) { s_pref = 0; s_rem = NCAND; s_cnt = 0; s_eq = 0; }
    __syncthreads();

    unsigned pmask = 0;
#pragma unroll
    for (int pass = 0; pass < 4; ++pass) {
        int shift = 24 - pass * 8;
        hist[t] = 0;
        __syncthreads();
        unsigned pref = (unsigned)s_pref;
        for (int e = t; e < Lv; e += 256) {
            unsigned k = keys[e];
            if ((k & pmask) == pref)
                atomicAdd(&hist[(k >> shift) & 255], 1);
        }
        __syncthreads();
        if (t < 32) {
            int lane = t;
            int h8[8]; int sl = 0;
#pragma unroll
            for (int bb = 0; bb < 8; ++bb) { h8[bb] = hist[lane * 8 + bb]; sl += h8[bb]; }
            int suf = sl;
#pragma unroll
            for (int o = 1; o < 32; o <<= 1) {
                int v = __shfl_down_sync(0xffffffffu, suf, o);
                if (lane + o < 32) suf += v;
            }
            int above = suf - sl;
            int rem = s_rem;
            __syncwarp();
            int run = 0;
#pragma unroll
            for (int bb = 7; bb >= 0; --bb) {
                run += h8[bb];
                int S = above + run;
                if (S >= rem && S - h8[bb] < rem) {
                    s_pref = (int)(pref | ((unsigned)(lane * 8 + bb) << shift));
                    s_remN = rem - (S - h8[bb]);
                }
            }
        }
        __syncthreads();
        if (t == 0) s_rem = s_remN;
        pmask |= (255u << shift);
        __syncthreads();
    }
    unsigned T = (unsigned)s_pref;
    int ceq = s_rem;
    for (int e = t; e < Lv; e += 256) {
        unsigned k = keys[e];
        if (k > T) {
            int pos = atomicAdd(&s_cnt, 1);
            cand_sm[pos] = e;
        } else if (k == T) {
            int p = atomicAdd(&s_eq, 1);
            if (p < ceq) {
                int pos = atomicAdd(&s_cnt, 1);
                cand_sm[pos] = e;
            }
        }
    }
    __syncthreads();

    // ---- exact fp32 rescore: 8 warps x 12 rounds (96 candidates) ----
    {
        int w = t >> 5, lane = t & 31;
        int grp = lane >> 3, j = lane & 7;
        const int is64 = g_is64;
        const long long* i64 = (const long long*)idxraw;
        const int*       i32 = (const int*)idxraw;
#pragma unroll 1
        for (int r = 0; r < NCAND / 8; ++r) {
            int c = r * 8 + w;
            int i = cand_sm[c];
            int rows[10];
#pragma unroll
            for (int p = 0; p < 10; ++p) {
                int s = p * 4 + grp;
                rows[p] = is64 ? (int)i64[i * SKv + s] : i32[i * SKv + s];
            }
            float4 kv[10][2];
#pragma unroll
            for (int p = 0; p < 10; ++p) {
                const float* kr = Kt + ((((b << 11) + rows[p]) * Hv + h) << 6) + j * 8;
                kv[p][0] = *(const float4*)(kr);
                kv[p][1] = *(const float4*)(kr + 4);
            }
            const float* qr = Q + ((((b << 11) + i) * Hv + h) << 6);
            float4 qa = *(const float4*)(qr + j * 8);
            float4 qb = *(const float4*)(qr + j * 8 + 4);

            float lmax = -FLT_MAX, lsum = 0.f;
#pragma unroll
            for (int p = 0; p < 10; ++p) {
                float4 ka = kv[p][0], kb = kv[p][1];
                float d = qa.x * ka.x + qa.y * ka.y + qa.z * ka.z + qa.w * ka.w
                        + qb.x * kb.x + qb.y * kb.y + qb.z * kb.z + qb.w * kb.w;
                d += __shfl_xor_sync(0xffffffffu, d, 1);
                d += __shfl_xor_sync(0xffffffffu, d, 2);
                d += __shfl_xor_sync(0xffffffffu, d, 4);
                lmax = fmaxf(lmax, d);
                lsum += d;
            }
            lmax = fmaxf(lmax, __shfl_xor_sync(0xffffffffu, lmax, 8));
            lmax = fmaxf(lmax, __shfl_xor_sync(0xffffffffu, lmax, 16));
            lsum += __shfl_xor_sync(0xffffffffu, lsum, 8);
            lsum += __shfl_xor_sync(0xffffffffu, lsum, 16);
            if (lane == 0)
                mex_sm[c] = lmax - lsum * (1.0f / (float)Lv);
        }
    }
    __syncthreads();

    // ---- top-40 set by rank counting, ordered by qi DESC ----
    if (t < NCAND) {
        float mv = mex_sm[t];
        int   ci = cand_sm[t];
        int rank = 0;
#pragma unroll
        for (int jj = 0; jj < NCAND; ++jj) {
            float ov = mex_sm[jj];
            int   oi = cand_sm[jj];
            rank += (ov > mv || (ov == mv && oi < ci)) ? 1 : 0;
        }
        selqi[t] = (rank < Uv) ? ci : -1;
    }
    __syncthreads();
    if (t < NCAND && selqi[t] >= 0) {
        int ci = selqi[t];
        int pos = 0;
#pragma unroll
        for (int jj = 0; jj < NCAND; ++jj)
            pos += (selqi[jj] > ci) ? 1 : 0;    // larger qi first
        g_Mtop[bh * Uv + pos] = ci;
    }
}

// ============ K-D: [0,512): causal attention (R7: CK=128, fp32 smem, 8 warps x 5u);
//              [512,768): cumsum writer ============
#define KS4 68   // K row stride (float4-aligned, conflict-free LDS.128)
#define VS2 66   // V row stride (float2, conflict-free LDS.64)
#define OFF_V  (CK * KS4)
#define OFF_Q  (OFF_V + CK * VS2)
#define OFF_P  (OFF_Q + Uv * 64)
#define OFF_QI (OFF_P + Uv * CK)
#define SMEM_ATTN ((OFF_QI + Uv) * 4)

__global__ void k_cumAttn(const float* __restrict__ Q, const float* __restrict__ Kt,
                          const float* __restrict__ Vt, float* __restrict__ out) {
    if (blockIdx.x >= ATTN_BLOCKS) {
        // ---- cum2: cumsum with chunk offset ----
        int bid = blockIdx.x - ATTN_BLOCKS;
        int bh = bid >> 3, cg = bid & 7;
        int b = bh >> 3, h = bh & 7;
        int sub = threadIdx.x >> 6, d = threadIdx.x & 63;
        int chunk = cg * 4 + sub;
        int base = (((b * Lv + chunk * CROWS) * Hv + h) << 6) + d;
        const int stride = Hv * Dv;
        float run = g_part[(bh * NCH + chunk) * Dv + d];
        for (int r0 = 0; r0 < CROWS; r0 += 8) {
            float v[8];
#pragma unroll
            for (int q = 0; q < 8; ++q) v[q] = Vt[base + (r0 + q) * stride];
#pragma unroll
            for (int q = 0; q < 8; ++q) { run += v[q]; out[base + (r0 + q) * stride] = run; }
        }
        return;
    }

    extern __shared__ float sm[];
    float* Ksm = sm;
    float* Vsm = sm + OFF_V;
    float* qsm = sm + OFF_Q;
    float* psm = sm + OFF_P;
    int*   qism = (int*)(sm + OFF_QI);

    int bid = blockIdx.x;
    int bh = bid >> 4, c = bid & 15;
    int b = bh >> 3, h = bh & 7;
    int t = threadIdx.x;
    int cbase = c * CK;

    if (t < Uv) qism[t] = g_Mtop[bh * Uv + t];
    int n_act = __syncthreads_count(t < Uv && qism[t] >= cbase);
    if (n_act == 0) return;   // uniform

    const int kbase = ((b * Lv + cbase) * Hv + h) << 6;
    for (int e = t; e < CK * 16; e += 256) {
        int r = e >> 4, d4 = (e & 15) * 4;
        *(float4*)&Ksm[r * KS4 + d4] = *(const float4*)(Kt + kbase + r * (Hv * Dv) + d4);
        float4 vv = *(const float4*)(Vt + kbase + r * (Hv * Dv) + d4);
        Vsm[r * VS2 + d4 + 0] = vv.x; Vsm[r * VS2 + d4 + 1] = vv.y;
        Vsm[r * VS2 + d4 + 2] = vv.z; Vsm[r * VS2 + d4 + 3] = vv.w;
    }
    for (int e = t; e < Uv * 16; e += 256) {
        int u = e >> 4, d4 = (e & 15) * 4;
        int qi = qism[u];
        float4 qv = *(const float4*)(Q + (((b * Lv + qi) * Hv + h) << 6) + d4);
        qv.x *= SCALEF; qv.y *= SCALEF; qv.z *= SCALEF; qv.w *= SCALEF;
        *(float4*)&qsm[u * 64 + d4] = qv;
    }
    __syncthreads();

    int w = t >> 5, kt = t & 31;

    // ---- score phase: warp w owns u = 5w+j; lanes own k = kt + 32i ----
    if (qism[5 * w] >= cbase) {       // warp-uniform skip
        float acc[5][4];
#pragma unroll
        for (int j = 0; j < 5; ++j)
#pragma unroll
            for (int i = 0; i < 4; ++i) acc[j][i] = 0.f;

#pragma unroll 4
        for (int dd4 = 0; dd4 < 16; ++dd4) {
            float4 k0 = *(const float4*)&Ksm[(kt     ) * KS4 + dd4 * 4];
            float4 k1 = *(const float4*)&Ksm[(kt + 32) * KS4 + dd4 * 4];
            float4 k2 = *(const float4*)&Ksm[(kt + 64) * KS4 + dd4 * 4];
            float4 k3 = *(const float4*)&Ksm[(kt + 96) * KS4 + dd4 * 4];
#pragma unroll
            for (int j = 0; j < 5; ++j) {
                float4 qf = *(const float4*)&qsm[(5 * w + j) * 64 + dd4 * 4];
                acc[j][0] += qf.x * k0.x + qf.y * k0.y + qf.z * k0.z + qf.w * k0.w;
                acc[j][1] += qf.x * k1.x + qf.y * k1.y + qf.z * k1.z + qf.w * k1.w;
                acc[j][2] += qf.x * k2.x + qf.y * k2.y + qf.z * k2.z + qf.w * k2.w;
                acc[j][3] += qf.x * k3.x + qf.y * k3.y + qf.z * k3.z + qf.w * k3.w;
            }
        }

#pragma unroll
        for (int j = 0; j < 5; ++j) {
            int u = 5 * w + j;
            int qi = qism[u];
            float s_l = 0.f;
#pragma unroll
            for (int i = 0; i < 4; ++i) {
                float p = (cbase + kt + 32 * i <= qi) ? __expf(acc[j][i]) : 0.f;
                psm[u * CK + kt + 32 * i] = p;
                s_l += p;
            }
#pragma unroll
            for (int o = 16; o; o >>= 1) s_l += __shfl_xor_sync(0xffffffffu, s_l, o);
            if (kt == 0)
                g_accP[((bh * NC + c) * Uv + u) * 66 + 64] = s_l;
        }
    }
    __syncthreads();

    // ---- PV phase: warp g owns u = 5g+j, lanes own 2 d ----
    int g = w, d2 = kt * 2;
    if (qism[5 * g] >= cbase) {
        float fa0[5], fa1[5];
#pragma unroll
        for (int j = 0; j < 5; ++j) { fa0[j] = 0.f; fa1[j] = 0.f; }

#pragma unroll 4
        for (int kk = 0; kk < 32; ++kk) {
            float2 v0 = *(const float2*)&Vsm[(kk * 4 + 0) * VS2 + d2];
            float2 v1 = *(const float2*)&Vsm[(kk * 4 + 1) * VS2 + d2];
            float2 v2 = *(const float2*)&Vsm[(kk * 4 + 2) * VS2 + d2];
            float2 v3 = *(const float2*)&Vsm[(kk * 4 + 3) * VS2 + d2];
#pragma unroll
            for (int j = 0; j < 5; ++j) {
                float4 pf = *(const float4*)&psm[(5 * g + j) * CK + kk * 4];
                fa0[j] += pf.x * v0.x + pf.y * v1.x + pf.z * v2.x + pf.w * v3.x;
                fa1[j] += pf.x * v0.y + pf.y * v1.y + pf.z * v2.y + pf.w * v3.y;
            }
        }
#pragma unroll
        for (int j = 0; j < 5; ++j) {
            int u = 5 * g + j;
            *(float2*)&g_accP[((bh * NC + c) * Uv + u) * 66 + d2] = make_float2(fa0[j], fa1[j]);
        }
    }
}

// ============ K-E: merge partials (causal chunks only), normalize, scatter ============
__global__ void k_attnM(float* __restrict__ out) {
    int bid = blockIdx.x;            // 128 blocks: 4 per bh
    int bh = bid >> 2, q4 = bid & 3;
    int b = bh >> 3, h = bh & 7;
    int t = threadIdx.x;
    for (int e = t; e < 10 * Dv; e += 256) {
        int u = q4 * 10 + (e >> 6), dd = e & 63;
        int qi = g_Mtop[bh * Uv + u];
        int ncu = (qi >> 7) + 1;     // chunks 0..qi/CK inclusive (CK=128)
        float a = 0.f, s = 0.f;
#pragma unroll 4
        for (int c = 0; c < ncu; ++c) {
            const float* base = &g_accP[((bh * NC + c) * Uv + u) * 66];
            a += base[dd];
            s += base[64];
        }
        out[(((b * Lv + qi) * Hv + h) << 6) + dd] = a / s;
    }
}

extern "C" void kernel_launch(void* const* d_in, const int* in_sizes, int n_in,
                              void* d_out, int out_size) {
    const float* Q   = (const float*)d_in[0];
    const float* K   = (const float*)d_in[1];
    const float* V   = (const float*)d_in[2];
    const void*  IDX = d_in[3];
    float* out = (float*)d_out;

    cudaFuncSetAttribute(k_cumAttn, cudaFuncAttributeMaxDynamicSharedMemorySize, SMEM_ATTN);

    k_conv<<<KELEMS / (256 * 8), 256>>>(K, Q, (const int*)IDX);
    k_MbSum<<<MB_BLOCKS + SUM_BLOCKS, 256>>>(IDX, V);
    k_selScan<<<64, 256>>>(Q, K, IDX);
    k_cumAttn<<<ATTN_BLOCKS + CUM_BLOCKS, 256, SMEM_ATTN>>>(Q, K, V, out);
    k_attnM<<<BHv * 4, 256>>>(out);
}

// round 15
// speedup vs baseline: 1.1991x; 1.0698x over previous
#include <cuda_runtime.h>
#include <cuda_bf16.h>
#include <float.h>

// Problem constants
#define Bv 4
#define Lv 2048
#define Hv 8
#define Dv 64
#define SKv 40      // sample_k
#define Uv 40       // top-u
#define NCAND 96    // int8-approx margin (validated exact-equivalent in R10/R14)
#define BHv 32
#define NCH 32      // cumsum chunks (64 rows each)
#define CROWS 64
#define CK 128      // attention key-chunk size
#define NC 16       // Lv / CK
#define SCALEF 0.125f
#define KELEMS (Bv * Lv * Hv * Dv)
#define KSCALE (5.5f / 127.0f)
#define KINV   (127.0f / 5.5f)

#define MB_BLOCKS 8192
#define SUM_BLOCKS 256
#define ATTN_BLOCKS (BHv * NC)   // 512
#define CUM_BLOCKS 256

// -------- scratch --------
__device__ float        g_M[BHv * Lv];
__device__ int          g_Mtop[BHv * Uv];      // sorted by qi DESCENDING
__device__ float        g_part[BHv * NCH * Dv];
__device__ float        g_accP[BHv * NC * Uv * 66];
__device__ uint4        g_K8[KELEMS / 16];     // int8 K shadow (64B rows)
__device__ uint4        g_Q8[KELEMS / 16];     // int8 Q shadow (per-row scale)
__device__ float        g_qs[KELEMS / 64];     // Q row scales (amax/127)
__device__ int          g_done[BHv];           // attention-block completion counters
__device__ int          g_is64;

// ============ K-A: int8 K+Q shadows + dtype detect + counter reset ============
__global__ void k_conv(const float* __restrict__ Kt, const float* __restrict__ Q,
                       const int* __restrict__ idx32) {
    if (blockIdx.x == 0 && threadIdx.x < 32) {
        int lane = threadIdx.x;
        g_done[lane] = 0;                       // reset per launch (graph replay safe)
        int bad = 0;
        for (int j = lane; j < 64; j += 32)
            bad |= (idx32[2 * j + 1] != 0);
        unsigned any = __ballot_sync(0xffffffffu, bad);
        if (lane == 0) g_is64 = (any == 0) ? 1 : 0;
    }
    int tid = blockIdx.x * 256 + threadIdx.x;
    int idx = tid * 8;

    // ---- K: global-scale int8 ----
    {
        float4 a = *(const float4*)(Kt + idx);
        float4 b = *(const float4*)(Kt + idx + 4);
        float v[8] = {a.x, a.y, a.z, a.w, b.x, b.y, b.z, b.w};
        unsigned w0 = 0, w1 = 0;
#pragma unroll
        for (int e = 0; e < 4; ++e) {
            int q = __float2int_rn(fminf(fmaxf(v[e] * KINV, -127.f), 127.f));
            w0 |= ((unsigned)q & 0xFFu) << (e * 8);
        }
#pragma unroll
        for (int e = 0; e < 4; ++e) {
            int q = __float2int_rn(fminf(fmaxf(v[4 + e] * KINV, -127.f), 127.f));
            w1 |= ((unsigned)q & 0xFFu) << (e * 8);
        }
        ((uint2*)g_K8)[idx >> 3] = make_uint2(w0, w1);
    }

    // ---- Q: per-row (64-elem) scale int8; 8 aligned threads per row ----
    {
        float4 a = *(const float4*)(Q + idx);
        float4 b = *(const float4*)(Q + idx + 4);
        float v[8] = {a.x, a.y, a.z, a.w, b.x, b.y, b.z, b.w};
        float amax = 0.f;
#pragma unroll
        for (int e = 0; e < 8; ++e) amax = fmaxf(amax, fabsf(v[e]));
        amax = fmaxf(amax, __shfl_xor_sync(0xffffffffu, amax, 1));
        amax = fmaxf(amax, __shfl_xor_sync(0xffffffffu, amax, 2));
        amax = fmaxf(amax, __shfl_xor_sync(0xffffffffu, amax, 4));
        float inv = (amax > 0.f) ? (127.f / amax) : 0.f;
        unsigned w0 = 0, w1 = 0;
#pragma unroll
        for (int e = 0; e < 4; ++e) {
            int q = __float2int_rn(fminf(fmaxf(v[e] * inv, -127.f), 127.f));
            w0 |= ((unsigned)q & 0xFFu) << (e * 8);
        }
#pragma unroll
        for (int e = 0; e < 4; ++e) {
            int q = __float2int_rn(fminf(fmaxf(v[4 + e] * inv, -127.f), 127.f));
            w1 |= ((unsigned)q & 0xFFu) << (e * 8);
        }
        ((uint2*)g_Q8)[idx >> 3] = make_uint2(w0, w1);
        if ((threadIdx.x & 7) == 0)
            g_qs[idx >> 6] = amax * (1.f / 127.f);
    }
}

// ============ K-B: approx M (int8 dp4a gather, pre-quantized Q) ++ V chunk sums ============
__global__ void k_MbSum(const void* __restrict__ idxraw, const float* __restrict__ V) {
    if (blockIdx.x < MB_BLOCKS) {
        int warp = (blockIdx.x * 256 + threadIdx.x) >> 5;
        int i  = warp & (Lv - 1);
        int bh = warp >> 11;
        int b = bh >> 3, h = bh & 7;
        int lane = threadIdx.x & 31;
        int grp = lane >> 2;    // 0..7
        int j4  = lane & 3;     // 0..3

        const int is64 = g_is64;
        const long long* i64 = (const long long*)idxraw;
        const int*       i32 = (const int*)idxraw;

        int rows[5];
#pragma unroll
        for (int p = 0; p < 5; ++p) {
            int s = p * 8 + grp;
            rows[p] = is64 ? (int)i64[i * SKv + s] : i32[i * SKv + s];
        }
        uint4 kw[5];
#pragma unroll
        for (int p = 0; p < 5; ++p)
            kw[p] = g_K8[((((b << 11) + rows[p]) * Hv + h) << 2) + j4];
        int qrow = ((b << 11) + i) * Hv + h;
        uint4 qv4 = g_Q8[(qrow << 2) + j4];
        float dscale = g_qs[qrow] * KSCALE;

        float lmax = -FLT_MAX, lsum = 0.f;
#pragma unroll
        for (int p = 0; p < 5; ++p) {
            int di = 0;
            di = __dp4a((int)kw[p].x, (int)qv4.x, di);
            di = __dp4a((int)kw[p].y, (int)qv4.y, di);
            di = __dp4a((int)kw[p].z, (int)qv4.z, di);
            di = __dp4a((int)kw[p].w, (int)qv4.w, di);
            di += __shfl_xor_sync(0xffffffffu, di, 1);
            di += __shfl_xor_sync(0xffffffffu, di, 2);
            float d = (float)di * dscale;
            lmax = fmaxf(lmax, d);
            lsum += d;
        }
        lmax = fmaxf(lmax, __shfl_xor_sync(0xffffffffu, lmax, 4));
        lmax = fmaxf(lmax, __shfl_xor_sync(0xffffffffu, lmax, 8));
        lmax = fmaxf(lmax, __shfl_xor_sync(0xffffffffu, lmax, 16));
        lsum += __shfl_xor_sync(0xffffffffu, lsum, 4);
        lsum += __shfl_xor_sync(0xffffffffu, lsum, 8);
        lsum += __shfl_xor_sync(0xffffffffu, lsum, 16);
        if (lane == 0)
            g_M[bh * Lv + i] = lmax - lsum * (1.0f / (float)Lv);
    } else {
        int bid = blockIdx.x - MB_BLOCKS;
        int bh = bid >> 3, cg = bid & 7;
        int b = bh >> 3, h = bh & 7;
        int sub = threadIdx.x >> 6, d = threadIdx.x & 63;
        int chunk = cg * 4 + sub;
        int base = (((b * Lv + chunk * CROWS) * Hv + h) << 6) + d;
        const int stride = Hv * Dv;
        float run = 0.f;
        for (int r0 = 0; r0 < CROWS; r0 += 8) {
            float v[8];
#pragma unroll
            for (int q = 0; q < 8; ++q) v[q] = V[base + (r0 + q) * stride];
#pragma unroll
            for (int q = 0; q < 8; ++q) run += v[q];
        }
        g_part[(bh * NCH + chunk) * Dv + d] = run;
    }
}

// ============ K-C: sel96 -> exact rescore -> top40 (qi desc) ++ chunk scan ============
// 512 threads: 16 warps -> 6 rescore rounds.
__device__ __forceinline__ unsigned f2u_mono(float f) {
    unsigned u = __float_as_uint(f);
    return (u & 0x80000000u) ? ~u : (u | 0x80000000u);
}

__global__ void k_selScan(const float* __restrict__ Q, const float* __restrict__ Kt,
                          const void* __restrict__ idxraw) {
    __shared__ unsigned keys[Lv];
    __shared__ int hist[256];
    __shared__ int cand_sm[NCAND];
    __shared__ float mex_sm[NCAND];
    __shared__ int selqi[NCAND];
    __shared__ int s_pref, s_rem, s_remN, s_cnt, s_eq;

    if (blockIdx.x >= 32) {
        // ---- scanB: exclusive scan of 32 chunk partials, full-MLP ----
        int bh = blockIdx.x - 32;
        int d = threadIdx.x;
        if (d < 64) {
            float v[NCH];
#pragma unroll
            for (int c = 0; c < NCH; ++c) v[c] = g_part[(bh * NCH + c) * Dv + d];
            float ex = 0.f;
#pragma unroll
            for (int c = 0; c < NCH; ++c) { float tv = v[c]; v[c] = ex; ex += tv; }
#pragma unroll
            for (int c = 0; c < NCH; ++c) g_part[(bh * NCH + c) * Dv + d] = v[c];
        }
        return;
    }

    int bh = blockIdx.x, t = threadIdx.x;
    int b = bh >> 3, h = bh & 7;

    for (int e = t; e < Lv; e += 512)
        keys[e] = f2u_mono(g_M[bh * Lv + e]);
    if (t == 0) { s_pref = 0; s_rem = NCAND; s_cnt = 0; s_eq = 0; }
    __syncthreads();

    unsigned pmask = 0;
#pragma unroll
    for (int pass = 0; pass < 4; ++pass) {
        int shift = 24 - pass * 8;
        if (t < 256) hist[t] = 0;
        __syncthreads();
        unsigned pref = (unsigned)s_pref;
        for (int e = t; e < Lv; e += 512) {
            unsigned k = keys[e];
            if ((k & pmask) == pref)
                atomicAdd(&hist[(k >> shift) & 255], 1);
        }
        __syncthreads();
        if (t < 32) {
            int lane = t;
            int h8[8]; int sl = 0;
#pragma unroll
            for (int bb = 0; bb < 8; ++bb) { h8[bb] = hist[lane * 8 + bb]; sl += h8[bb]; }
            int suf = sl;
#pragma unroll
            for (int o = 1; o < 32; o <<= 1) {
                int v = __shfl_down_sync(0xffffffffu, suf, o);
                if (lane + o < 32) suf += v;
            }
            int above = suf - sl;
            int rem = s_rem;
            __syncwarp();
            int run = 0;
#pragma unroll
            for (int bb = 7; bb >= 0; --bb) {
                run += h8[bb];
                int S = above + run;
                if (S >= rem && S - h8[bb] < rem) {
                    s_pref = (int)(pref | ((unsigned)(lane * 8 + bb) << shift));
                    s_remN = rem - (S - h8[bb]);
                }
            }
        }
        __syncthreads();
        if (t == 0) s_rem = s_remN;
        pmask |= (255u << shift);
        __syncthreads();
    }
    unsigned T = (unsigned)s_pref;
    int ceq = s_rem;
    for (int e = t; e < Lv; e += 512) {
        unsigned k = keys[e];
        if (k > T) {
            int pos = atomicAdd(&s_cnt, 1);
            cand_sm[pos] = e;
        } else if (k == T) {
            int p = atomicAdd(&s_eq, 1);
            if (p < ceq) {
                int pos = atomicAdd(&s_cnt, 1);
                cand_sm[pos] = e;
            }
        }
    }
    __syncthreads();

    // ---- exact fp32 rescore: 16 warps x 6 rounds ----
    {
        int w = t >> 5, lane = t & 31;
        int grp = lane >> 3, j = lane & 7;
        const int is64 = g_is64;
        const long long* i64 = (const long long*)idxraw;
        const int*       i32 = (const int*)idxraw;
#pragma unroll 1
        for (int r = 0; r < NCAND / 16; ++r) {
            int c = r * 16 + w;
            int i = cand_sm[c];
            int rows[10];
#pragma unroll
            for (int p = 0; p < 10; ++p) {
                int s = p * 4 + grp;
                rows[p] = is64 ? (int)i64[i * SKv + s] : i32[i * SKv + s];
            }
            float4 kv[10][2];
#pragma unroll
            for (int p = 0; p < 10; ++p) {
                const float* kr = Kt + ((((b << 11) + rows[p]) * Hv + h) << 6) + j * 8;
                kv[p][0] = *(const float4*)(kr);
                kv[p][1] = *(const float4*)(kr + 4);
            }
            const float* qr = Q + ((((b << 11) + i) * Hv + h) << 6);
            float4 qa = *(const float4*)(qr + j * 8);
            float4 qb = *(const float4*)(qr + j * 8 + 4);

            float lmax = -FLT_MAX, lsum = 0.f;
#pragma unroll
            for (int p = 0; p < 10; ++p) {
                float4 ka = kv[p][0], kb = kv[p][1];
                float d = qa.x * ka.x + qa.y * ka.y + qa.z * ka.z + qa.w * ka.w
                        + qb.x * kb.x + qb.y * kb.y + qb.z * kb.z + qb.w * kb.w;
                d += __shfl_xor_sync(0xffffffffu, d, 1);
                d += __shfl_xor_sync(0xffffffffu, d, 2);
                d += __shfl_xor_sync(0xffffffffu, d, 4);
                lmax = fmaxf(lmax, d);
                lsum += d;
            }
            lmax = fmaxf(lmax, __shfl_xor_sync(0xffffffffu, lmax, 8));
            lmax = fmaxf(lmax, __shfl_xor_sync(0xffffffffu, lmax, 16));
            lsum += __shfl_xor_sync(0xffffffffu, lsum, 8);
            lsum += __shfl_xor_sync(0xffffffffu, lsum, 16);
            if (lane == 0)
                mex_sm[c] = lmax - lsum * (1.0f / (float)Lv);
        }
    }
    __syncthreads();

    // ---- top-40 set by rank counting, ordered by qi DESC ----
    if (t < NCAND) {
        float mv = mex_sm[t];
        int   ci = cand_sm[t];
        int rank = 0;
#pragma unroll
        for (int jj = 0; jj < NCAND; ++jj) {
            float ov = mex_sm[jj];
            int   oi = cand_sm[jj];
            rank += (ov > mv || (ov == mv && oi < ci)) ? 1 : 0;
        }
        selqi[t] = (rank < Uv) ? ci : -1;
    }
    __syncthreads();
    if (t < NCAND && selqi[t] >= 0) {
        int ci = selqi[t];
        int pos = 0;
#pragma unroll
        for (int jj = 0; jj < NCAND; ++jj)
            pos += (selqi[jj] > ci) ? 1 : 0;    // larger qi first
        g_Mtop[bh * Uv + pos] = ci;
    }
}

// ============ K-D: [0,512): causal attention + fused last-block merge;
//              [512,768): cumsum writer (skips selected rows) ============
#define KS4 68   // K row stride (float4-aligned, conflict-free LDS.128)
#define VS2 66   // V row stride (float2, conflict-free LDS.64)
#define OFF_V  (CK * KS4)
#define OFF_Q  (OFF_V + CK * VS2)
#define OFF_P  (OFF_Q + Uv * 64)
#define OFF_QI (OFF_P + Uv * CK)
#define SMEM_ATTN ((OFF_QI + Uv + 1) * 4)

__global__ void k_cumAttn(const float* __restrict__ Q, const float* __restrict__ Kt,
                          const float* __restrict__ Vt, float* __restrict__ out) {
    if (blockIdx.x >= ATTN_BLOCKS) {
        // ---- cum2: cumsum writer; skip rows owned by the attention scatter ----
        __shared__ unsigned selmask[Lv / 32];   // 64 words
        int bid = blockIdx.x - ATTN_BLOCKS;
        int bh = bid >> 3, cg = bid & 7;
        int b = bh >> 3, h = bh & 7;
        int t = threadIdx.x;
        if (t < Lv / 32) selmask[t] = 0;
        __syncthreads();
        if (t < Uv) {
            int qi = g_Mtop[bh * Uv + t];
            atomicOr(&selmask[qi >> 5], 1u << (qi & 31));
        }
        __syncthreads();

        int sub = t >> 6, d = t & 63;
        int chunk = cg * 4 + sub;
        int row0 = chunk * CROWS;
        int base = (((b * Lv + row0) * Hv + h) << 6) + d;
        const int stride = Hv * Dv;
        float run = g_part[(bh * NCH + chunk) * Dv + d];
        for (int r0 = 0; r0 < CROWS; r0 += 8) {
            float v[8];
#pragma unroll
            for (int q = 0; q < 8; ++q) v[q] = Vt[base + (r0 + q) * stride];
#pragma unroll
            for (int q = 0; q < 8; ++q) {
                run += v[q];
                int row = row0 + r0 + q;
                if (!((selmask[row >> 5] >> (row & 31)) & 1u))
                    out[base + (r0 + q) * stride] = run;
            }
        }
        return;
    }

    extern __shared__ float sm[];
    float* Ksm = sm;
    float* Vsm = sm + OFF_V;
    float* qsm = sm + OFF_Q;
    float* psm = sm + OFF_P;
    int*   qism = (int*)(sm + OFF_QI);
    int*   s_last = (int*)(sm + OFF_QI + Uv);

    int bid = blockIdx.x;
    int bh = bid >> 4, c = bid & 15;
    int b = bh >> 3, h = bh & 7;
    int t = threadIdx.x;
    int cbase = c * CK;

    if (t < Uv) qism[t] = g_Mtop[bh * Uv + t];
    int n_act = __syncthreads_count(t < Uv && qism[t] >= cbase);

    if (n_act > 0) {   // uniform branch
        const int kbase = ((b * Lv + cbase) * Hv + h) << 6;
        for (int e = t; e < CK * 16; e += 256) {
            int r = e >> 4, d4 = (e & 15) * 4;
            *(float4*)&Ksm[r * KS4 + d4] = *(const float4*)(Kt + kbase + r * (Hv * Dv) + d4);
            float4 vv = *(const float4*)(Vt + kbase + r * (Hv * Dv) + d4);
            Vsm[r * VS2 + d4 + 0] = vv.x; Vsm[r * VS2 + d4 + 1] = vv.y;
            Vsm[r * VS2 + d4 + 2] = vv.z; Vsm[r * VS2 + d4 + 3] = vv.w;
        }
        for (int e = t; e < Uv * 16; e += 256) {
            int u = e >> 4, d4 = (e & 15) * 4;
            int qi = qism[u];
            float4 qv = *(const float4*)(Q + (((b * Lv + qi) * Hv + h) << 6) + d4);
            qv.x *= SCALEF; qv.y *= SCALEF; qv.z *= SCALEF; qv.w *= SCALEF;
            *(float4*)&qsm[u * 64 + d4] = qv;
        }
        __syncthreads();

        int w = t >> 5, kt = t & 31;

        // ---- score phase: warp w owns u = 5w+j; lanes own k = kt + 32i ----
        if (qism[5 * w] >= cbase) {       // warp-uniform skip
            float acc[5][4];
#pragma unroll
            for (int j = 0; j < 5; ++j)
#pragma unroll
                for (int i = 0; i < 4; ++i) acc[j][i] = 0.f;

#pragma unroll 4
            for (int dd4 = 0; dd4 < 16; ++dd4) {
                float4 k0 = *(const float4*)&Ksm[(kt     ) * KS4 + dd4 * 4];
                float4 k1 = *(const float4*)&Ksm[(kt + 32) * KS4 + dd4 * 4];
                float4 k2 = *(const float4*)&Ksm[(kt + 64) * KS4 + dd4 * 4];
                float4 k3 = *(const float4*)&Ksm[(kt + 96) * KS4 + dd4 * 4];
#pragma unroll
                for (int j = 0; j < 5; ++j) {
                    float4 qf = *(const float4*)&qsm[(5 * w + j) * 64 + dd4 * 4];
                    acc[j][0] += qf.x * k0.x + qf.y * k0.y + qf.z * k0.z + qf.w * k0.w;
                    acc[j][1] += qf.x * k1.x + qf.y * k1.y + qf.z * k1.z + qf.w * k1.w;
                    acc[j][2] += qf.x * k2.x + qf.y * k2.y + qf.z * k2.z + qf.w * k2.w;
                    acc[j][3] += qf.x * k3.x + qf.y * k3.y + qf.z * k3.z + qf.w * k3.w;
                }
            }

#pragma unroll
            for (int j = 0; j < 5; ++j) {
                int u = 5 * w + j;
                int qi = qism[u];
                float s_l = 0.f;
#pragma unroll
                for (int i = 0; i < 4; ++i) {
                    float p = (cbase + kt + 32 * i <= qi) ? __expf(acc[j][i]) : 0.f;
                    psm[u * CK + kt + 32 * i] = p;
                    s_l += p;
                }
#pragma unroll
                for (int o = 16; o; o >>= 1) s_l += __shfl_xor_sync(0xffffffffu, s_l, o);
                if (kt == 0)
                    g_accP[((bh * NC + c) * Uv + u) * 66 + 64] = s_l;
            }
        }
        __syncthreads();

        // ---- PV phase: warp g owns u = 5g+j, lanes own 2 d ----
        int g = w, d2 = kt * 2;
        if (qism[5 * g] >= cbase) {
            float fa0[5], fa1[5];
#pragma unroll
            for (int j = 0; j < 5; ++j) { fa0[j] = 0.f; fa1[j] = 0.f; }

#pragma unroll 4
            for (int kk = 0; kk < 32; ++kk) {
                float2 v0 = *(const float2*)&Vsm[(kk * 4 + 0) * VS2 + d2];
                float2 v1 = *(const float2*)&Vsm[(kk * 4 + 1) * VS2 + d2];
                float2 v2 = *(const float2*)&Vsm[(kk * 4 + 2) * VS2 + d2];
                float2 v3 = *(const float2*)&Vsm[(kk * 4 + 3) * VS2 + d2];
#pragma unroll
                for (int j = 0; j < 5; ++j) {
                    float4 pf = *(const float4*)&psm[(5 * g + j) * CK + kk * 4];
                    fa0[j] += pf.x * v0.x + pf.y * v1.x + pf.z * v2.x + pf.w * v3.x;
                    fa1[j] += pf.x * v0.y + pf.y * v1.y + pf.z * v2.y + pf.w * v3.y;
                }
            }
#pragma unroll
            for (int j = 0; j < 5; ++j) {
                int u = 5 * g + j;
                *(float2*)&g_accP[((bh * NC + c) * Uv + u) * 66 + d2] = make_float2(fa0[j], fa1[j]);
            }
        }
    }

    // ---- completion counter; last block of this bh performs the merge ----
    __threadfence();
    __syncthreads();
    if (t == 0)
        *s_last = (atomicAdd(&g_done[bh], 1) == NC - 1) ? 1 : 0;
    __syncthreads();
    if (*s_last) {
        for (int e = t; e < Uv * Dv; e += 256) {
            int u = e >> 6, dd = e & 63;
            int qi = qism[u];
            int ncu = (qi >> 7) + 1;     // chunks 0..qi/CK inclusive
            float a = 0.f, s = 0.f;
#pragma unroll 4
            for (int cc = 0; cc < ncu; ++cc) {
                const float* base = &g_accP[((bh * NC + cc) * Uv + u) * 66];
                a += base[dd];
                s += base[64];
            }
            out[(((b * Lv + qi) * Hv + h) << 6) + dd] = a / s;
        }
    }
}

extern "C" void kernel_launch(void* const* d_in, const int* in_sizes, int n_in,
                              void* d_out, int out_size) {
    const float* Q   = (const float*)d_in[0];
    const float* K   = (const float*)d_in[1];
    const float* V   = (const float*)d_in[2];
    const void*  IDX = d_in[3];
    float* out = (float*)d_out;

    cudaFuncSetAttribute(k_cumAttn, cudaFuncAttributeMaxDynamicSharedMemorySize, SMEM_ATTN);

    k_conv<<<KELEMS / (256 * 8), 256>>>(K, Q, (const int*)IDX);
    k_MbSum<<<MB_BLOCKS + SUM_BLOCKS, 256>>>(IDX, V);
    k_selScan<<<64, 512>>>(Q, K, IDX);
    k_cumAttn<<<ATTN_BLOCKS + CUM_BLOCKS, 256, SMEM_ATTN>>>(Q, K, V, out);
}